// round 4
// baseline (speedup 1.0000x reference)
#include <cuda_runtime.h>
#include <cuda_bf16.h>
#include <math.h>

// ---------------------------------------------------------------------------
// Problem constants (fixed shapes from reference setup_inputs)
// ---------------------------------------------------------------------------
#define NN 100000
#define EE 3200000
#define F0 512
#define F1 256
#define F2 256
#define F3 64

// ---------------------------------------------------------------------------
// Scratch: __device__ globals (no allocations allowed)
// ---------------------------------------------------------------------------
__device__ float g_A[(size_t)NN * 256];   // ping
__device__ float g_B[(size_t)NN * 256];   // pong
__device__ float g_C[(size_t)NN * 64];    // pre-softmax support
__device__ int   g_rowptr[NN + 1];
__device__ int   g_cursor[NN];            // doubles as histogram counts
__device__ int   g_cols[EE];
__device__ float g_vals[EE];
__device__ int   g_bsums[128];

// ---------------------------------------------------------------------------
// CSR build: histogram -> exclusive scan -> scatter
// ---------------------------------------------------------------------------
__global__ void k_zero_int(int* p, int n) {
    int i = blockIdx.x * blockDim.x + threadIdx.x;
    if (i < n) p[i] = 0;
}

__global__ void k_hist(const int* __restrict__ erow) {
    int e = blockIdx.x * blockDim.x + threadIdx.x;
    if (e < EE) atomicAdd(&g_cursor[erow[e]], 1);
}

// Per-block exclusive scan over counts (n = NN+1 logical elems, counts[i>=NN]=0)
__global__ void k_scan_block(int n) {
    int tid  = threadIdx.x;
    int i    = blockIdx.x * 1024 + tid;
    int v    = (i < NN) ? g_cursor[i] : 0;
    int lane = tid & 31, warp = tid >> 5;
    int x = v;
    #pragma unroll
    for (int o = 1; o < 32; o <<= 1) {
        int y = __shfl_up_sync(0xFFFFFFFFu, x, o);
        if (lane >= o) x += y;
    }
    __shared__ int wsum[32];
    if (lane == 31) wsum[warp] = x;
    __syncthreads();
    if (warp == 0) {
        int w = wsum[lane];
        #pragma unroll
        for (int o = 1; o < 32; o <<= 1) {
            int y = __shfl_up_sync(0xFFFFFFFFu, w, o);
            if (lane >= o) w += y;
        }
        wsum[lane] = w;
    }
    __syncthreads();
    int incl = x + (warp > 0 ? wsum[warp - 1] : 0);
    if (i < n) g_rowptr[i] = incl - v;  // exclusive within block
    if (tid == 1023) g_bsums[blockIdx.x] = incl;
}

__global__ void k_scan_spine(int nb) {   // single block, 128 threads
    int tid = threadIdx.x;
    int lane = tid & 31, warp = tid >> 5;
    int v = (tid < nb) ? g_bsums[tid] : 0;
    int x = v;
    #pragma unroll
    for (int o = 1; o < 32; o <<= 1) {
        int y = __shfl_up_sync(0xFFFFFFFFu, x, o);
        if (lane >= o) x += y;
    }
    __shared__ int ws[4];
    if (lane == 31) ws[warp] = x;
    __syncthreads();
    int off = 0;
    for (int w = 0; w < warp; w++) off += ws[w];
    if (tid < nb) g_bsums[tid] = (x + off) - v;  // exclusive
}

__global__ void k_scan_add(int n) {
    int i = blockIdx.x * 1024 + threadIdx.x;
    if (i < n) g_rowptr[i] += g_bsums[blockIdx.x];
}

__global__ void k_scatter(const int* __restrict__ erow,
                          const int* __restrict__ ecol,
                          const float* __restrict__ eval) {
    int e = blockIdx.x * blockDim.x + threadIdx.x;
    if (e < EE) {
        int r = erow[e];
        int p = g_rowptr[r] + atomicAdd(&g_cursor[r], 1);
        g_cols[p] = ecol[e];
        g_vals[p] = eval[e];
    }
}

// ---------------------------------------------------------------------------
// Dense GEMM: C[M,N] = A[M,K] @ W[K,N]   (fp32)
// Templated tile, double-buffered SMEM with register-staged global prefetch.
// Main config: 128x128 tile, 8x8 microtile, 256 threads
//   -> per k-step: LDS 16KB (128 cyc) == FMA 16384 (128 cyc), balanced.
// ---------------------------------------------------------------------------
template<int BM, int BN, int BK, int TM, int TN>
__global__ __launch_bounds__((BM/TM)*(BN/TN)) void k_gemm(
    const float* __restrict__ A, const float* __restrict__ W,
    float* __restrict__ C, int M, int N, int K)
{
    constexpr int NT = (BM/TM)*(BN/TN);
    constexpr int A4 = BM*BK/4/NT;   // float4 loads per thread for A tile
    constexpr int B4 = BK*BN/4/NT;   // float4 loads per thread for W tile

    __shared__ float As[2][BK][BM];
    __shared__ float Bs[2][BK][BN];

    const int tid = threadIdx.x;
    const int m0 = blockIdx.y * BM, n0 = blockIdx.x * BN;
    const int tm = (tid / (BN/TN)) * TM;
    const int tn = (tid % (BN/TN)) * TN;

    float acc[TM][TN];
    #pragma unroll
    for (int i = 0; i < TM; i++)
        #pragma unroll
        for (int j = 0; j < TN; j++) acc[i][j] = 0.f;

    float4 stgA[A4], stgB[B4];

    // --- global -> register staging for tile at k0 ---
    #define LOAD_G(k0)                                                        \
    {                                                                         \
        _Pragma("unroll")                                                     \
        for (int j = 0; j < A4; j++) {                                        \
            int f = tid + j * NT;                                             \
            int r = f / (BK/4), c = (f % (BK/4)) * 4;                         \
            int gr = m0 + r;                                                  \
            stgA[j] = (gr < M) ? *(const float4*)&A[(size_t)gr*K + (k0) + c]  \
                               : make_float4(0.f,0.f,0.f,0.f);                \
        }                                                                     \
        _Pragma("unroll")                                                     \
        for (int j = 0; j < B4; j++) {                                        \
            int f = tid + j * NT;                                             \
            int r = f / (BN/4), c = (f % (BN/4)) * 4;                         \
            stgB[j] = *(const float4*)&W[(size_t)((k0)+r)*N + n0 + c];        \
        }                                                                     \
    }

    // --- register -> shared store into buffer b ---
    #define STORE_S(b)                                                        \
    {                                                                         \
        _Pragma("unroll")                                                     \
        for (int j = 0; j < A4; j++) {                                        \
            int f = tid + j * NT;                                             \
            int r = f / (BK/4), c = (f % (BK/4)) * 4;                         \
            As[b][c+0][r] = stgA[j].x; As[b][c+1][r] = stgA[j].y;             \
            As[b][c+2][r] = stgA[j].z; As[b][c+3][r] = stgA[j].w;             \
        }                                                                     \
        _Pragma("unroll")                                                     \
        for (int j = 0; j < B4; j++) {                                        \
            int f = tid + j * NT;                                             \
            int r = f / (BN/4), c = (f % (BN/4)) * 4;                         \
            *(float4*)&Bs[b][r][c] = stgB[j];                                 \
        }                                                                     \
    }

    LOAD_G(0);
    STORE_S(0);
    __syncthreads();

    int buf = 0;
    for (int k0 = 0; k0 < K; k0 += BK) {
        if (k0 + BK < K) LOAD_G(k0 + BK);   // prefetch next tile while computing

        #pragma unroll
        for (int k = 0; k < BK; k++) {
            float ar[TM], br[TN];
            #pragma unroll
            for (int i = 0; i < TM; i += 4)
                *(float4*)&ar[i] = *(const float4*)&As[buf][k][tm + i];
            #pragma unroll
            for (int j = 0; j < TN; j += 4)
                *(float4*)&br[j] = *(const float4*)&Bs[buf][k][tn + j];
            #pragma unroll
            for (int i = 0; i < TM; i++)
                #pragma unroll
                for (int j = 0; j < TN; j++)
                    acc[i][j] = fmaf(ar[i], br[j], acc[i][j]);
        }

        if (k0 + BK < K) {
            STORE_S(buf ^ 1);
            __syncthreads();
            buf ^= 1;
        }
    }

    #pragma unroll
    for (int i = 0; i < TM; i++) {
        int row = m0 + tm + i;
        if (row < M) {
            #pragma unroll
            for (int j = 0; j < TN; j += 4) {
                float4 v = make_float4(acc[i][j], acc[i][j+1],
                                       acc[i][j+2], acc[i][j+3]);
                *(float4*)&C[(size_t)row * N + n0 + tn + j] = v;
            }
        }
    }
    #undef LOAD_G
    #undef STORE_S
}

// ---------------------------------------------------------------------------
// SpMM F=256: out[row] = sum_e val_e * sup[col_e]  (+bias, relu)
// One block per row, thread = feature column. Atomic-free.
// ---------------------------------------------------------------------------
__global__ __launch_bounds__(256) void k_spmm256(
    const float* __restrict__ sup, const float* __restrict__ bias,
    float* __restrict__ out)
{
    int row = blockIdx.x;
    int tid = threadIdx.x;
    int s = g_rowptr[row], e = g_rowptr[row + 1];

    float acc0 = 0.f, acc1 = 0.f;
    int i = s;
    for (; i + 4 <= e; i += 4) {
        int   c0 = g_cols[i],     c1 = g_cols[i + 1];
        int   c2 = g_cols[i + 2], c3 = g_cols[i + 3];
        float v0 = g_vals[i],     v1 = g_vals[i + 1];
        float v2 = g_vals[i + 2], v3 = g_vals[i + 3];
        acc0 = fmaf(v0, sup[(size_t)c0 * 256 + tid], acc0);
        acc1 = fmaf(v1, sup[(size_t)c1 * 256 + tid], acc1);
        acc0 = fmaf(v2, sup[(size_t)c2 * 256 + tid], acc0);
        acc1 = fmaf(v3, sup[(size_t)c3 * 256 + tid], acc1);
    }
    for (; i < e; i++) {
        acc0 = fmaf(g_vals[i], sup[(size_t)g_cols[i] * 256 + tid], acc0);
    }
    float acc = acc0 + acc1 + bias[tid];
    acc = fmaxf(acc, 0.f);   // relu (both F=256 layers are relu'd)
    out[(size_t)row * 256 + tid] = acc;
}

// ---------------------------------------------------------------------------
// SpMM F=64 + bias + log_softmax, one block (64 threads) per row
// ---------------------------------------------------------------------------
__global__ __launch_bounds__(64) void k_spmm64_lsm(
    const float* __restrict__ sup, const float* __restrict__ b3,
    float* __restrict__ out)
{
    int row = blockIdx.x;
    int tid = threadIdx.x;
    int s = g_rowptr[row], e = g_rowptr[row + 1];

    float acc0 = 0.f, acc1 = 0.f;
    int i = s;
    for (; i + 4 <= e; i += 4) {
        int   c0 = g_cols[i],     c1 = g_cols[i + 1];
        int   c2 = g_cols[i + 2], c3 = g_cols[i + 3];
        float v0 = g_vals[i],     v1 = g_vals[i + 1];
        float v2 = g_vals[i + 2], v3 = g_vals[i + 3];
        acc0 = fmaf(v0, sup[(size_t)c0 * 64 + tid], acc0);
        acc1 = fmaf(v1, sup[(size_t)c1 * 64 + tid], acc1);
        acc0 = fmaf(v2, sup[(size_t)c2 * 64 + tid], acc0);
        acc1 = fmaf(v3, sup[(size_t)c3 * 64 + tid], acc1);
    }
    for (; i < e; i++) {
        acc0 = fmaf(g_vals[i], sup[(size_t)g_cols[i] * 64 + tid], acc0);
    }
    float acc = acc0 + acc1 + b3[tid];

    int lane = tid & 31, warp = tid >> 5;
    __shared__ float wred[2];

    // row max
    float m = acc;
    #pragma unroll
    for (int o = 16; o > 0; o >>= 1)
        m = fmaxf(m, __shfl_xor_sync(0xFFFFFFFFu, m, o));
    if (lane == 0) wred[warp] = m;
    __syncthreads();
    float M = fmaxf(wred[0], wred[1]);
    __syncthreads();

    // sum of exp
    float ex = expf(acc - M);
    float sum = ex;
    #pragma unroll
    for (int o = 16; o > 0; o >>= 1)
        sum += __shfl_xor_sync(0xFFFFFFFFu, sum, o);
    if (lane == 0) wred[warp] = sum;
    __syncthreads();
    float S = wred[0] + wred[1];

    out[(size_t)row * 64 + tid] = acc - M - logf(S);
}

// ---------------------------------------------------------------------------
// Launch
// ---------------------------------------------------------------------------
extern "C" void kernel_launch(void* const* d_in, const int* in_sizes, int n_in,
                              void* d_out, int out_size)
{
    const float* x    = (const float*)d_in[0];
    const int*   erow = (const int*)  d_in[1];
    const int*   ecol = (const int*)  d_in[2];
    const float* eval = (const float*)d_in[3];
    const float* W1   = (const float*)d_in[4];
    const float* b1   = (const float*)d_in[5];
    const float* W2   = (const float*)d_in[6];
    const float* b2   = (const float*)d_in[7];
    const float* W3   = (const float*)d_in[8];
    const float* b3   = (const float*)d_in[9];
    float* out = (float*)d_out;

    // resolve device-global addresses (host-side query, capture-safe)
    float *dA, *dB, *dC;
    int *dCur;
    cudaGetSymbolAddress((void**)&dA,   g_A);
    cudaGetSymbolAddress((void**)&dB,   g_B);
    cudaGetSymbolAddress((void**)&dC,   g_C);
    cudaGetSymbolAddress((void**)&dCur, g_cursor);

    const int NB_SCAN = (NN + 1 + 1023) / 1024;   // 98
    const int EB = (EE + 255) / 256;

    // --- CSR build ---
    k_zero_int<<<(NN + 255) / 256, 256>>>(dCur, NN);
    k_hist<<<EB, 256>>>(erow);
    k_scan_block<<<NB_SCAN, 1024>>>(NN + 1);
    k_scan_spine<<<1, 128>>>(NB_SCAN);
    k_scan_add<<<NB_SCAN, 1024>>>(NN + 1);
    k_zero_int<<<(NN + 255) / 256, 256>>>(dCur, NN);
    k_scatter<<<EB, 256>>>(erow, ecol, eval);

    // --- layer 1: s1 = x @ W1 ; h1 = relu(spmm(s1) + b1) ---
    {
        dim3 grid(F1 / 128, (NN + 127) / 128);
        k_gemm<128,128,16,8,8><<<grid, 256>>>(x, W1, dA, NN, F1, F0);
    }
    k_spmm256<<<NN, 256>>>(dA, b1, dB);

    // --- layer 2: s2 = h1 @ W2 ; h2 = relu(spmm(s2) + b2) ---
    {
        dim3 grid(F2 / 128, (NN + 127) / 128);
        k_gemm<128,128,16,8,8><<<grid, 256>>>(dB, W2, dA, NN, F2, F1);
    }
    k_spmm256<<<NN, 256>>>(dA, b2, dB);

    // --- layer 3: s3 = h2 @ W3 ; out = log_softmax(spmm(s3) + b3) ---
    {
        dim3 grid(F3 / 64, (NN + 127) / 128);
        k_gemm<128,64,16,8,4><<<grid, 256>>>(dB, W3, dC, NN, F3, F2);
    }
    k_spmm64_lsm<<<NN, 64>>>(dC, b3, out);
}

// round 5
// speedup vs baseline: 1.6035x; 1.6035x over previous
#include <cuda_runtime.h>
#include <cuda_bf16.h>
#include <math.h>
#include <stdint.h>

// ---------------------------------------------------------------------------
// Problem constants (fixed shapes from reference setup_inputs)
// ---------------------------------------------------------------------------
#define NN 100000
#define EE 3200000
#define F0 512
#define F1 256
#define F2 256
#define F3 64

// ---------------------------------------------------------------------------
// Scratch: __device__ globals (no allocations allowed)
// ---------------------------------------------------------------------------
__device__ float g_X [(size_t)NN * F0];   // tf32-rounded copy of x
__device__ float g_A [(size_t)NN * 256];  // GEMM output / spmm support
__device__ float g_B [(size_t)NN * 256];  // spmm output (tf32-rounded)
__device__ float g_C [(size_t)NN * 64];   // pre-softmax support
__device__ float g_W1c[F0 * F1];
__device__ float g_W2c[F1 * F2];
__device__ float g_W3c[F2 * F3];
__device__ int   g_rowptr[NN + 1];
__device__ int   g_cursor[NN];            // doubles as histogram counts
__device__ int   g_cols[EE];
__device__ float g_vals[EE];
__device__ int   g_bsums[128];

__device__ __forceinline__ uint32_t f2tf32(float x) {
    uint32_t u;
    asm("cvt.rna.tf32.f32 %0, %1;" : "=r"(u) : "f"(x));
    return u;
}

// ---------------------------------------------------------------------------
// tf32 rounding kernel (vectorized)
// ---------------------------------------------------------------------------
__global__ void k_cvt_rna(const float* __restrict__ src, float* __restrict__ dst, int n4) {
    int i = blockIdx.x * blockDim.x + threadIdx.x;
    if (i < n4) {
        float4 v = ((const float4*)src)[i];
        v.x = __uint_as_float(f2tf32(v.x));
        v.y = __uint_as_float(f2tf32(v.y));
        v.z = __uint_as_float(f2tf32(v.z));
        v.w = __uint_as_float(f2tf32(v.w));
        ((float4*)dst)[i] = v;
    }
}

// ---------------------------------------------------------------------------
// CSR build: histogram -> exclusive scan -> scatter
// ---------------------------------------------------------------------------
__global__ void k_zero_int(int* p, int n) {
    int i = blockIdx.x * blockDim.x + threadIdx.x;
    if (i < n) p[i] = 0;
}

__global__ void k_hist(const int* __restrict__ erow) {
    int e = blockIdx.x * blockDim.x + threadIdx.x;
    if (e < EE) atomicAdd(&g_cursor[erow[e]], 1);
}

__global__ void k_scan_block(int n) {
    int tid  = threadIdx.x;
    int i    = blockIdx.x * 1024 + tid;
    int v    = (i < NN) ? g_cursor[i] : 0;
    int lane = tid & 31, warp = tid >> 5;
    int x = v;
    #pragma unroll
    for (int o = 1; o < 32; o <<= 1) {
        int y = __shfl_up_sync(0xFFFFFFFFu, x, o);
        if (lane >= o) x += y;
    }
    __shared__ int wsum[32];
    if (lane == 31) wsum[warp] = x;
    __syncthreads();
    if (warp == 0) {
        int w = wsum[lane];
        #pragma unroll
        for (int o = 1; o < 32; o <<= 1) {
            int y = __shfl_up_sync(0xFFFFFFFFu, w, o);
            if (lane >= o) w += y;
        }
        wsum[lane] = w;
    }
    __syncthreads();
    int incl = x + (warp > 0 ? wsum[warp - 1] : 0);
    if (i < n) g_rowptr[i] = incl - v;
    if (tid == 1023) g_bsums[blockIdx.x] = incl;
}

__global__ void k_scan_spine(int nb) {
    int tid = threadIdx.x;
    int lane = tid & 31, warp = tid >> 5;
    int v = (tid < nb) ? g_bsums[tid] : 0;
    int x = v;
    #pragma unroll
    for (int o = 1; o < 32; o <<= 1) {
        int y = __shfl_up_sync(0xFFFFFFFFu, x, o);
        if (lane >= o) x += y;
    }
    __shared__ int ws[4];
    if (lane == 31) ws[warp] = x;
    __syncthreads();
    int off = 0;
    for (int w = 0; w < warp; w++) off += ws[w];
    if (tid < nb) g_bsums[tid] = (x + off) - v;
}

__global__ void k_scan_add(int n) {
    int i = blockIdx.x * 1024 + threadIdx.x;
    if (i < n) g_rowptr[i] += g_bsums[blockIdx.x];
}

__global__ void k_scatter(const int* __restrict__ erow,
                          const int* __restrict__ ecol,
                          const float* __restrict__ eval) {
    int e = blockIdx.x * blockDim.x + threadIdx.x;
    if (e < EE) {
        int r = erow[e];
        int p = g_rowptr[r] + atomicAdd(&g_cursor[r], 1);
        g_cols[p] = ecol[e];
        g_vals[p] = eval[e];
    }
}

// ---------------------------------------------------------------------------
// TF32 tensor-core GEMM: C[M,N] = A[M,K] @ W[K,N]
// mma.sync.m16n8k8.tf32, cp.async double-buffered SMEM, conflict-free pads.
// Inputs MUST already be tf32-rounded (cvt.rna) fp32 values.
// ---------------------------------------------------------------------------
template<int BM, int BN, int WM, int WN>
__global__ __launch_bounds__((BM/WM)*(BN/WN)*32) void k_gemm_tc(
    const float* __restrict__ A, const float* __restrict__ W,
    float* __restrict__ C, int M, int N, int K)
{
    constexpr int BK  = 16;
    constexpr int NWARP = (BM/WM)*(BN/WN);
    constexpr int NT  = NWARP * 32;
    constexpr int AST = BK + 4;      // 20: A-frag LDS conflict-free
    constexpr int BST = BN + 8;      // stride%32==8: B-frag LDS conflict-free
    constexpr int ACH = BM*BK/4/NT;  // 16B chunks per thread (A tile)
    constexpr int BCH = BK*BN/4/NT;
    constexpr int MT  = WM/16, NTL = WN/8;

    __shared__ float As[2][BM][AST];
    __shared__ float Bs[2][BK][BST];

    const int tid  = threadIdx.x;
    const int lane = tid & 31, wid = tid >> 5;
    const int wm   = (wid % (BM/WM)) * WM;
    const int wn   = (wid / (BM/WM)) * WN;
    const int m0   = blockIdx.y * BM, n0 = blockIdx.x * BN;

    float acc[MT][NTL][4];
    #pragma unroll
    for (int i = 0; i < MT; i++)
        #pragma unroll
        for (int j = 0; j < NTL; j++)
            #pragma unroll
            for (int q = 0; q < 4; q++) acc[i][j][q] = 0.f;

    const int T = K / BK;

    // --- async tile loader ---
    #define ISSUE(t, buf)                                                       \
    {                                                                           \
        int k0 = (t) * BK;                                                      \
        _Pragma("unroll")                                                       \
        for (int j = 0; j < ACH; j++) {                                         \
            int f = tid + j * NT;                                               \
            int m = f >> 2, c = (f & 3) << 2;                                   \
            int gm = m0 + m;                                                    \
            const float* src = A + (size_t)(gm < M ? gm : 0) * K + k0 + c;      \
            uint32_t dst = (uint32_t)__cvta_generic_to_shared(&As[buf][m][c]);  \
            int sz = (gm < M) ? 16 : 0;                                         \
            asm volatile("cp.async.ca.shared.global [%0], [%1], 16, %2;\n"      \
                         :: "r"(dst), "l"(src), "r"(sz));                       \
        }                                                                       \
        _Pragma("unroll")                                                       \
        for (int j = 0; j < BCH; j++) {                                         \
            int f = tid + j * NT;                                               \
            int k = f / (BN/4), c = (f % (BN/4)) << 2;                          \
            const float* src = W + (size_t)(k0 + k) * N + n0 + c;               \
            uint32_t dst = (uint32_t)__cvta_generic_to_shared(&Bs[buf][k][c]);  \
            asm volatile("cp.async.ca.shared.global [%0], [%1], 16;\n"          \
                         :: "r"(dst), "l"(src));                                \
        }                                                                       \
        asm volatile("cp.async.commit_group;\n");                               \
    }

    ISSUE(0, 0);
    ISSUE(1, 1);                               // T >= 4 always here
    asm volatile("cp.async.wait_group 1;\n");
    __syncthreads();

    for (int t = 0; t < T; t++) {
        const int buf = t & 1;
        #pragma unroll
        for (int k8 = 0; k8 < 2; k8++) {
            const int kk   = k8 * 8 + (lane & 3);
            const int mrow = wm + (lane >> 2);
            uint32_t af[MT][4];
            #pragma unroll
            for (int mt = 0; mt < MT; mt++) {
                af[mt][0] = __float_as_uint(As[buf][mrow + mt*16    ][kk    ]);
                af[mt][1] = __float_as_uint(As[buf][mrow + mt*16 + 8][kk    ]);
                af[mt][2] = __float_as_uint(As[buf][mrow + mt*16    ][kk + 4]);
                af[mt][3] = __float_as_uint(As[buf][mrow + mt*16 + 8][kk + 4]);
            }
            #pragma unroll
            for (int nt = 0; nt < NTL; nt++) {
                const int ncol = wn + nt*8 + (lane >> 2);
                uint32_t b0 = __float_as_uint(Bs[buf][kk    ][ncol]);
                uint32_t b1 = __float_as_uint(Bs[buf][kk + 4][ncol]);
                #pragma unroll
                for (int mt = 0; mt < MT; mt++) {
                    asm volatile(
                        "mma.sync.aligned.m16n8k8.row.col.f32.tf32.tf32.f32 "
                        "{%0,%1,%2,%3},{%4,%5,%6,%7},{%8,%9},{%0,%1,%2,%3};\n"
                        : "+f"(acc[mt][nt][0]), "+f"(acc[mt][nt][1]),
                          "+f"(acc[mt][nt][2]), "+f"(acc[mt][nt][3])
                        : "r"(af[mt][0]), "r"(af[mt][1]),
                          "r"(af[mt][2]), "r"(af[mt][3]),
                          "r"(b0), "r"(b1));
                }
            }
        }
        __syncthreads();                        // all warps done reading buf
        if (t + 2 < T) { ISSUE(t + 2, buf); }
        else           { asm volatile("cp.async.commit_group;\n"); }
        asm volatile("cp.async.wait_group 1;\n");
        __syncthreads();
    }
    #undef ISSUE

    // epilogue: fp32 accumulators -> C
    #pragma unroll
    for (int mt = 0; mt < MT; mt++) {
        int r0 = m0 + wm + mt*16 + (lane >> 2);
        #pragma unroll
        for (int nt = 0; nt < NTL; nt++) {
            int cc = n0 + wn + nt*8 + (lane & 3)*2;
            if (r0 < M)
                *(float2*)&C[(size_t)r0 * N + cc] =
                    make_float2(acc[mt][nt][0], acc[mt][nt][1]);
            if (r0 + 8 < M)
                *(float2*)&C[(size_t)(r0 + 8) * N + cc] =
                    make_float2(acc[mt][nt][2], acc[mt][nt][3]);
        }
    }
}

// ---------------------------------------------------------------------------
// SpMM F=256: out[row] = sum_e val_e * sup[col_e]  (+bias, relu, tf32-round)
// One block per row, thread = feature column. Atomic-free.
// ---------------------------------------------------------------------------
__global__ __launch_bounds__(256) void k_spmm256(
    const float* __restrict__ sup, const float* __restrict__ bias,
    float* __restrict__ out)
{
    int row = blockIdx.x;
    int tid = threadIdx.x;
    int s = g_rowptr[row], e = g_rowptr[row + 1];

    float acc0 = 0.f, acc1 = 0.f;
    int i = s;
    for (; i + 4 <= e; i += 4) {
        int   c0 = g_cols[i],     c1 = g_cols[i + 1];
        int   c2 = g_cols[i + 2], c3 = g_cols[i + 3];
        float v0 = g_vals[i],     v1 = g_vals[i + 1];
        float v2 = g_vals[i + 2], v3 = g_vals[i + 3];
        acc0 = fmaf(v0, sup[(size_t)c0 * 256 + tid], acc0);
        acc1 = fmaf(v1, sup[(size_t)c1 * 256 + tid], acc1);
        acc0 = fmaf(v2, sup[(size_t)c2 * 256 + tid], acc0);
        acc1 = fmaf(v3, sup[(size_t)c3 * 256 + tid], acc1);
    }
    for (; i < e; i++) {
        acc0 = fmaf(g_vals[i], sup[(size_t)g_cols[i] * 256 + tid], acc0);
    }
    float acc = acc0 + acc1 + bias[tid];
    acc = fmaxf(acc, 0.f);
    // round to tf32: this value is the A-operand of the next tensor GEMM
    out[(size_t)row * 256 + tid] = __uint_as_float(f2tf32(acc));
}

// ---------------------------------------------------------------------------
// SpMM F=64 + bias + log_softmax, one block (64 threads) per row
// ---------------------------------------------------------------------------
__global__ __launch_bounds__(64) void k_spmm64_lsm(
    const float* __restrict__ sup, const float* __restrict__ b3,
    float* __restrict__ out)
{
    int row = blockIdx.x;
    int tid = threadIdx.x;
    int s = g_rowptr[row], e = g_rowptr[row + 1];

    float acc0 = 0.f, acc1 = 0.f;
    int i = s;
    for (; i + 4 <= e; i += 4) {
        int   c0 = g_cols[i],     c1 = g_cols[i + 1];
        int   c2 = g_cols[i + 2], c3 = g_cols[i + 3];
        float v0 = g_vals[i],     v1 = g_vals[i + 1];
        float v2 = g_vals[i + 2], v3 = g_vals[i + 3];
        acc0 = fmaf(v0, sup[(size_t)c0 * 64 + tid], acc0);
        acc1 = fmaf(v1, sup[(size_t)c1 * 64 + tid], acc1);
        acc0 = fmaf(v2, sup[(size_t)c2 * 64 + tid], acc0);
        acc1 = fmaf(v3, sup[(size_t)c3 * 64 + tid], acc1);
    }
    for (; i < e; i++) {
        acc0 = fmaf(g_vals[i], sup[(size_t)g_cols[i] * 64 + tid], acc0);
    }
    float acc = acc0 + acc1 + b3[tid];

    int lane = tid & 31, warp = tid >> 5;
    __shared__ float wred[2];

    float m = acc;
    #pragma unroll
    for (int o = 16; o > 0; o >>= 1)
        m = fmaxf(m, __shfl_xor_sync(0xFFFFFFFFu, m, o));
    if (lane == 0) wred[warp] = m;
    __syncthreads();
    float M = fmaxf(wred[0], wred[1]);
    __syncthreads();

    float ex = expf(acc - M);
    float sum = ex;
    #pragma unroll
    for (int o = 16; o > 0; o >>= 1)
        sum += __shfl_xor_sync(0xFFFFFFFFu, sum, o);
    if (lane == 0) wred[warp] = sum;
    __syncthreads();
    float S = wred[0] + wred[1];

    out[(size_t)row * 64 + tid] = acc - M - logf(S);
}

// ---------------------------------------------------------------------------
// Launch
// ---------------------------------------------------------------------------
extern "C" void kernel_launch(void* const* d_in, const int* in_sizes, int n_in,
                              void* d_out, int out_size)
{
    const float* x    = (const float*)d_in[0];
    const int*   erow = (const int*)  d_in[1];
    const int*   ecol = (const int*)  d_in[2];
    const float* eval = (const float*)d_in[3];
    const float* W1   = (const float*)d_in[4];
    const float* b1   = (const float*)d_in[5];
    const float* W2   = (const float*)d_in[6];
    const float* b2   = (const float*)d_in[7];
    const float* W3   = (const float*)d_in[8];
    const float* b3   = (const float*)d_in[9];
    float* out = (float*)d_out;

    float *dX, *dA, *dB, *dC, *dW1, *dW2, *dW3;
    int *dCur;
    cudaGetSymbolAddress((void**)&dX,   g_X);
    cudaGetSymbolAddress((void**)&dA,   g_A);
    cudaGetSymbolAddress((void**)&dB,   g_B);
    cudaGetSymbolAddress((void**)&dC,   g_C);
    cudaGetSymbolAddress((void**)&dW1,  g_W1c);
    cudaGetSymbolAddress((void**)&dW2,  g_W2c);
    cudaGetSymbolAddress((void**)&dW3,  g_W3c);
    cudaGetSymbolAddress((void**)&dCur, g_cursor);

    const int NB_SCAN = (NN + 1 + 1023) / 1024;
    const int EB = (EE + 255) / 256;

    // --- tf32 pre-rounding of GEMM inputs (unbiased rna) ---
    {
        int n4 = NN * F0 / 4;
        k_cvt_rna<<<(n4 + 255) / 256, 256>>>(x, dX, n4);
        n4 = F0 * F1 / 4;
        k_cvt_rna<<<(n4 + 255) / 256, 256>>>(W1, dW1, n4);
        n4 = F1 * F2 / 4;
        k_cvt_rna<<<(n4 + 255) / 256, 256>>>(W2, dW2, n4);
        n4 = F2 * F3 / 4;
        k_cvt_rna<<<(n4 + 255) / 256, 256>>>(W3, dW3, n4);
    }

    // --- CSR build ---
    k_zero_int<<<(NN + 255) / 256, 256>>>(dCur, NN);
    k_hist<<<EB, 256>>>(erow);
    k_scan_block<<<NB_SCAN, 1024>>>(NN + 1);
    k_scan_spine<<<1, 128>>>(NB_SCAN);
    k_scan_add<<<NB_SCAN, 1024>>>(NN + 1);
    k_zero_int<<<(NN + 255) / 256, 256>>>(dCur, NN);
    k_scatter<<<EB, 256>>>(erow, ecol, eval);

    const int MB = (NN + 127) / 128;   // 782 row-blocks

    // --- layer 1: s1 = x @ W1 ; h1 = tf32(relu(spmm(s1) + b1)) ---
    k_gemm_tc<128,128,64,64><<<dim3(F1/128, MB), 128>>>(dX, dW1, dA, NN, F1, F0);
    k_spmm256<<<NN, 256>>>(dA, b1, dB);

    // --- layer 2 ---
    k_gemm_tc<128,128,64,64><<<dim3(F2/128, MB), 128>>>(dB, dW2, dA, NN, F2, F1);
    k_spmm256<<<NN, 256>>>(dA, b2, dB);

    // --- layer 3 + log_softmax ---
    k_gemm_tc<128,64,64,32><<<dim3(F3/64, MB), 128>>>(dB, dW3, dC, NN, F3, F2);
    k_spmm64_lsm<<<NN, 64>>>(dC, b3, out);
}

// round 6
// speedup vs baseline: 2.6501x; 1.6527x over previous
#include <cuda_runtime.h>
#include <cuda_bf16.h>
#include <math.h>
#include <stdint.h>

// ---------------------------------------------------------------------------
// Problem constants
// ---------------------------------------------------------------------------
#define NN 100000
#define EE 3200000
#define F0 512
#define F1 256
#define F2 256
#define F3 64

// ---------------------------------------------------------------------------
// Scratch (__device__ globals; no allocations allowed)
// ---------------------------------------------------------------------------
__device__ uint32_t g_Sbf[(size_t)NN * 128];   // bf16x2 support, F=256 (51.2 MB)
__device__ float    g_H  [(size_t)NN * 256];   // fp32 (tf32-rounded) activations
__device__ uint32_t g_Cbf[(size_t)NN * 32];    // bf16x2 support, F=64
__device__ float    g_W1c[F0 * F1];
__device__ float    g_W2c[F1 * F2];
__device__ float    g_W3c[F2 * F3];
__device__ int      g_rowptr[NN + 1];
__device__ int      g_cursor[NN];
__device__ int      g_cols[EE];
__device__ float    g_vals[EE];
__device__ int      g_bsums[128];

__device__ __forceinline__ uint32_t f2tf32(float x) {
    uint32_t u;
    asm("cvt.rna.tf32.f32 %0, %1;" : "=r"(u) : "f"(x));
    return u;
}
// bf16x2 -> two fp32 (exact, pure ALU)
__device__ __forceinline__ float2 bf2x_to_f2(uint32_t u) {
    float2 f;
    f.x = __uint_as_float(u << 16);
    f.y = __uint_as_float(u & 0xffff0000u);
    return f;
}

// ---------------------------------------------------------------------------
// tf32 rounding kernel (weights only — small)
// ---------------------------------------------------------------------------
__global__ void k_cvt_rna(const float* __restrict__ src, float* __restrict__ dst, int n4) {
    int i = blockIdx.x * blockDim.x + threadIdx.x;
    if (i < n4) {
        float4 v = ((const float4*)src)[i];
        v.x = __uint_as_float(f2tf32(v.x));
        v.y = __uint_as_float(f2tf32(v.y));
        v.z = __uint_as_float(f2tf32(v.z));
        v.w = __uint_as_float(f2tf32(v.w));
        ((float4*)dst)[i] = v;
    }
}

// ---------------------------------------------------------------------------
// CSR build: histogram -> exclusive scan -> scatter
// ---------------------------------------------------------------------------
__global__ void k_zero_int(int* p, int n) {
    int i = blockIdx.x * blockDim.x + threadIdx.x;
    if (i < n) p[i] = 0;
}

__global__ void k_hist(const int* __restrict__ erow) {
    int e = blockIdx.x * blockDim.x + threadIdx.x;
    if (e < EE) atomicAdd(&g_cursor[erow[e]], 1);
}

__global__ void k_scan_block(int n) {
    int tid  = threadIdx.x;
    int i    = blockIdx.x * 1024 + tid;
    int v    = (i < NN) ? g_cursor[i] : 0;
    int lane = tid & 31, warp = tid >> 5;
    int x = v;
    #pragma unroll
    for (int o = 1; o < 32; o <<= 1) {
        int y = __shfl_up_sync(0xFFFFFFFFu, x, o);
        if (lane >= o) x += y;
    }
    __shared__ int wsum[32];
    if (lane == 31) wsum[warp] = x;
    __syncthreads();
    if (warp == 0) {
        int w = wsum[lane];
        #pragma unroll
        for (int o = 1; o < 32; o <<= 1) {
            int y = __shfl_up_sync(0xFFFFFFFFu, w, o);
            if (lane >= o) w += y;
        }
        wsum[lane] = w;
    }
    __syncthreads();
    int incl = x + (warp > 0 ? wsum[warp - 1] : 0);
    if (i < n) g_rowptr[i] = incl - v;
    if (tid == 1023) g_bsums[blockIdx.x] = incl;
}

__global__ void k_scan_spine(int nb) {
    int tid = threadIdx.x;
    int lane = tid & 31, warp = tid >> 5;
    int v = (tid < nb) ? g_bsums[tid] : 0;
    int x = v;
    #pragma unroll
    for (int o = 1; o < 32; o <<= 1) {
        int y = __shfl_up_sync(0xFFFFFFFFu, x, o);
        if (lane >= o) x += y;
    }
    __shared__ int ws[4];
    if (lane == 31) ws[warp] = x;
    __syncthreads();
    int off = 0;
    for (int w = 0; w < warp; w++) off += ws[w];
    if (tid < nb) g_bsums[tid] = (x + off) - v;
}

__global__ void k_scan_add(int n) {
    int i = blockIdx.x * 1024 + threadIdx.x;
    if (i < n) g_rowptr[i] += g_bsums[blockIdx.x];
}

__global__ void k_scatter(const int* __restrict__ erow,
                          const int* __restrict__ ecol,
                          const float* __restrict__ eval) {
    int e = blockIdx.x * blockDim.x + threadIdx.x;
    if (e < EE) {
        int r = erow[e];
        int p = g_rowptr[r] + atomicAdd(&g_cursor[r], 1);
        g_cols[p] = ecol[e];
        g_vals[p] = eval[e];
    }
}

// ---------------------------------------------------------------------------
// TF32 tensor-core GEMM: C[M,N] = A[M,K] @ W[K,N]
// mma.sync.m16n8k8.tf32, cp.async double-buffered, conflict-free padding.
// RND_A: apply cvt.rna.tf32 to A-fragments (for un-prerounded inputs).
// OUT_BF16: write C as packed bf16x2 instead of fp32.
// ---------------------------------------------------------------------------
template<int BM, int BN, int WM, int WN, bool RND_A, bool OUT_BF16>
__global__ __launch_bounds__((BM/WM)*(BN/WN)*32) void k_gemm_tc(
    const float* __restrict__ A, const float* __restrict__ W,
    void* __restrict__ Cv, int M, int N, int K)
{
    constexpr int BK  = 16;
    constexpr int NWARP = (BM/WM)*(BN/WN);
    constexpr int NT  = NWARP * 32;
    constexpr int AST = BK + 4;
    constexpr int BST = BN + 8;
    constexpr int ACH = BM*BK/4/NT;
    constexpr int BCH = BK*BN/4/NT;
    constexpr int MT  = WM/16, NTL = WN/8;

    __shared__ float As[2][BM][AST];
    __shared__ float Bs[2][BK][BST];

    const int tid  = threadIdx.x;
    const int lane = tid & 31, wid = tid >> 5;
    const int wm   = (wid % (BM/WM)) * WM;
    const int wn   = (wid / (BM/WM)) * WN;
    const int m0   = blockIdx.y * BM, n0 = blockIdx.x * BN;

    float acc[MT][NTL][4];
    #pragma unroll
    for (int i = 0; i < MT; i++)
        #pragma unroll
        for (int j = 0; j < NTL; j++)
            #pragma unroll
            for (int q = 0; q < 4; q++) acc[i][j][q] = 0.f;

    const int T = K / BK;

    #define ISSUE(t, buf)                                                       \
    {                                                                           \
        int k0 = (t) * BK;                                                      \
        _Pragma("unroll")                                                       \
        for (int j = 0; j < ACH; j++) {                                         \
            int f = tid + j * NT;                                               \
            int m = f >> 2, c = (f & 3) << 2;                                   \
            int gm = m0 + m;                                                    \
            const float* src = A + (size_t)(gm < M ? gm : 0) * K + k0 + c;      \
            uint32_t dst = (uint32_t)__cvta_generic_to_shared(&As[buf][m][c]);  \
            int sz = (gm < M) ? 16 : 0;                                         \
            asm volatile("cp.async.ca.shared.global [%0], [%1], 16, %2;\n"      \
                         :: "r"(dst), "l"(src), "r"(sz));                       \
        }                                                                       \
        _Pragma("unroll")                                                       \
        for (int j = 0; j < BCH; j++) {                                         \
            int f = tid + j * NT;                                               \
            int k = f / (BN/4), c = (f % (BN/4)) << 2;                          \
            const float* src = W + (size_t)(k0 + k) * N + n0 + c;               \
            uint32_t dst = (uint32_t)__cvta_generic_to_shared(&Bs[buf][k][c]);  \
            asm volatile("cp.async.ca.shared.global [%0], [%1], 16;\n"          \
                         :: "r"(dst), "l"(src));                                \
        }                                                                       \
        asm volatile("cp.async.commit_group;\n");                               \
    }

    ISSUE(0, 0);
    ISSUE(1, 1);
    asm volatile("cp.async.wait_group 1;\n");
    __syncthreads();

    for (int t = 0; t < T; t++) {
        const int buf = t & 1;
        #pragma unroll
        for (int k8 = 0; k8 < 2; k8++) {
            const int kk   = k8 * 8 + (lane & 3);
            const int mrow = wm + (lane >> 2);
            uint32_t af[MT][4];
            #pragma unroll
            for (int mt = 0; mt < MT; mt++) {
                float a0 = As[buf][mrow + mt*16    ][kk    ];
                float a1 = As[buf][mrow + mt*16 + 8][kk    ];
                float a2 = As[buf][mrow + mt*16    ][kk + 4];
                float a3 = As[buf][mrow + mt*16 + 8][kk + 4];
                if (RND_A) {
                    af[mt][0] = f2tf32(a0); af[mt][1] = f2tf32(a1);
                    af[mt][2] = f2tf32(a2); af[mt][3] = f2tf32(a3);
                } else {
                    af[mt][0] = __float_as_uint(a0); af[mt][1] = __float_as_uint(a1);
                    af[mt][2] = __float_as_uint(a2); af[mt][3] = __float_as_uint(a3);
                }
            }
            #pragma unroll
            for (int nt = 0; nt < NTL; nt++) {
                const int ncol = wn + nt*8 + (lane >> 2);
                uint32_t b0 = __float_as_uint(Bs[buf][kk    ][ncol]);
                uint32_t b1 = __float_as_uint(Bs[buf][kk + 4][ncol]);
                #pragma unroll
                for (int mt = 0; mt < MT; mt++) {
                    asm volatile(
                        "mma.sync.aligned.m16n8k8.row.col.f32.tf32.tf32.f32 "
                        "{%0,%1,%2,%3},{%4,%5,%6,%7},{%8,%9},{%0,%1,%2,%3};\n"
                        : "+f"(acc[mt][nt][0]), "+f"(acc[mt][nt][1]),
                          "+f"(acc[mt][nt][2]), "+f"(acc[mt][nt][3])
                        : "r"(af[mt][0]), "r"(af[mt][1]),
                          "r"(af[mt][2]), "r"(af[mt][3]),
                          "r"(b0), "r"(b1));
                }
            }
        }
        __syncthreads();
        if (t + 2 < T) { ISSUE(t + 2, buf); }
        else           { asm volatile("cp.async.commit_group;\n"); }
        asm volatile("cp.async.wait_group 1;\n");
        __syncthreads();
    }
    #undef ISSUE

    // epilogue
    #pragma unroll
    for (int mt = 0; mt < MT; mt++) {
        int r0 = m0 + wm + mt*16 + (lane >> 2);
        #pragma unroll
        for (int nt = 0; nt < NTL; nt++) {
            int cc = n0 + wn + nt*8 + (lane & 3)*2;
            if (OUT_BF16) {
                uint32_t* Cb = (uint32_t*)Cv;  // bf16x2-packed, N/2 per row
                if (r0 < M) {
                    __nv_bfloat162 p = __floats2bfloat162_rn(acc[mt][nt][0], acc[mt][nt][1]);
                    Cb[(size_t)r0 * (N/2) + cc/2] = *(uint32_t*)&p;
                }
                if (r0 + 8 < M) {
                    __nv_bfloat162 p = __floats2bfloat162_rn(acc[mt][nt][2], acc[mt][nt][3]);
                    Cb[(size_t)(r0 + 8) * (N/2) + cc/2] = *(uint32_t*)&p;
                }
            } else {
                float* C = (float*)Cv;
                if (r0 < M)
                    *(float2*)&C[(size_t)r0 * N + cc] =
                        make_float2(acc[mt][nt][0], acc[mt][nt][1]);
                if (r0 + 8 < M)
                    *(float2*)&C[(size_t)(r0 + 8) * N + cc] =
                        make_float2(acc[mt][nt][2], acc[mt][nt][3]);
            }
        }
    }
}

// ---------------------------------------------------------------------------
// SpMM F=256 over bf16 support: block(128)/row, thread handles 2 features.
// out = tf32( relu( sum val*sup[col] + bias ) )  (fp32 accumulate)
// ---------------------------------------------------------------------------
__global__ __launch_bounds__(128) void k_spmm256_bf(
    const uint32_t* __restrict__ supu, const float* __restrict__ bias,
    float* __restrict__ out)
{
    int row = blockIdx.x;
    int tid = threadIdx.x;
    int s = g_rowptr[row], e = g_rowptr[row + 1];

    float ax0 = 0.f, ay0 = 0.f, ax1 = 0.f, ay1 = 0.f;
    int i = s;
    for (; i + 4 <= e; i += 4) {
        int   c0 = g_cols[i],     c1 = g_cols[i + 1];
        int   c2 = g_cols[i + 2], c3 = g_cols[i + 3];
        float v0 = g_vals[i],     v1 = g_vals[i + 1];
        float v2 = g_vals[i + 2], v3 = g_vals[i + 3];
        float2 f0 = bf2x_to_f2(supu[(size_t)c0 * 128 + tid]);
        float2 f1 = bf2x_to_f2(supu[(size_t)c1 * 128 + tid]);
        float2 f2 = bf2x_to_f2(supu[(size_t)c2 * 128 + tid]);
        float2 f3 = bf2x_to_f2(supu[(size_t)c3 * 128 + tid]);
        ax0 = fmaf(v0, f0.x, ax0); ay0 = fmaf(v0, f0.y, ay0);
        ax1 = fmaf(v1, f1.x, ax1); ay1 = fmaf(v1, f1.y, ay1);
        ax0 = fmaf(v2, f2.x, ax0); ay0 = fmaf(v2, f2.y, ay0);
        ax1 = fmaf(v3, f3.x, ax1); ay1 = fmaf(v3, f3.y, ay1);
    }
    for (; i < e; i++) {
        float v = g_vals[i];
        float2 f = bf2x_to_f2(supu[(size_t)g_cols[i] * 128 + tid]);
        ax0 = fmaf(v, f.x, ax0); ay0 = fmaf(v, f.y, ay0);
    }
    float2 b = *(const float2*)&bias[2 * tid];
    float rx = fmaxf(ax0 + ax1 + b.x, 0.f);
    float ry = fmaxf(ay0 + ay1 + b.y, 0.f);
    float2 o;
    o.x = __uint_as_float(f2tf32(rx));
    o.y = __uint_as_float(f2tf32(ry));
    *(float2*)&out[(size_t)row * 256 + 2 * tid] = o;
}

// ---------------------------------------------------------------------------
// SpMM F=64 (bf16 support) + bias + log_softmax. Warp per row, 4 rows/block.
// ---------------------------------------------------------------------------
__global__ __launch_bounds__(128) void k_spmm64_lsm_bf(
    const uint32_t* __restrict__ supu, const float* __restrict__ b3,
    float* __restrict__ out)
{
    int lane = threadIdx.x & 31;
    int row  = blockIdx.x * 4 + (threadIdx.x >> 5);

    int s = g_rowptr[row], e = g_rowptr[row + 1];

    float ax0 = 0.f, ay0 = 0.f, ax1 = 0.f, ay1 = 0.f;
    int i = s;
    for (; i + 4 <= e; i += 4) {
        int   c0 = g_cols[i],     c1 = g_cols[i + 1];
        int   c2 = g_cols[i + 2], c3 = g_cols[i + 3];
        float v0 = g_vals[i],     v1 = g_vals[i + 1];
        float v2 = g_vals[i + 2], v3 = g_vals[i + 3];
        float2 f0 = bf2x_to_f2(supu[(size_t)c0 * 32 + lane]);
        float2 f1 = bf2x_to_f2(supu[(size_t)c1 * 32 + lane]);
        float2 f2 = bf2x_to_f2(supu[(size_t)c2 * 32 + lane]);
        float2 f3 = bf2x_to_f2(supu[(size_t)c3 * 32 + lane]);
        ax0 = fmaf(v0, f0.x, ax0); ay0 = fmaf(v0, f0.y, ay0);
        ax1 = fmaf(v1, f1.x, ax1); ay1 = fmaf(v1, f1.y, ay1);
        ax0 = fmaf(v2, f2.x, ax0); ay0 = fmaf(v2, f2.y, ay0);
        ax1 = fmaf(v3, f3.x, ax1); ay1 = fmaf(v3, f3.y, ay1);
    }
    for (; i < e; i++) {
        float v = g_vals[i];
        float2 f = bf2x_to_f2(supu[(size_t)g_cols[i] * 32 + lane]);
        ax0 = fmaf(v, f.x, ax0); ay0 = fmaf(v, f.y, ay0);
    }
    float2 b = *(const float2*)&b3[2 * lane];
    float rx = ax0 + ax1 + b.x;
    float ry = ay0 + ay1 + b.y;

    // warp log-softmax over 64 values (2 per lane)
    float m = fmaxf(rx, ry);
    #pragma unroll
    for (int o = 16; o > 0; o >>= 1)
        m = fmaxf(m, __shfl_xor_sync(0xFFFFFFFFu, m, o));
    float sum = expf(rx - m) + expf(ry - m);
    #pragma unroll
    for (int o = 16; o > 0; o >>= 1)
        sum += __shfl_xor_sync(0xFFFFFFFFu, sum, o);
    float ls = m + logf(sum);

    float2 o2 = make_float2(rx - ls, ry - ls);
    *(float2*)&out[(size_t)row * 64 + 2 * lane] = o2;
}

// ---------------------------------------------------------------------------
// Launch
// ---------------------------------------------------------------------------
extern "C" void kernel_launch(void* const* d_in, const int* in_sizes, int n_in,
                              void* d_out, int out_size)
{
    const float* x    = (const float*)d_in[0];
    const int*   erow = (const int*)  d_in[1];
    const int*   ecol = (const int*)  d_in[2];
    const float* eval = (const float*)d_in[3];
    const float* W1   = (const float*)d_in[4];
    const float* b1   = (const float*)d_in[5];
    const float* W2   = (const float*)d_in[6];
    const float* b2   = (const float*)d_in[7];
    const float* W3   = (const float*)d_in[8];
    const float* b3   = (const float*)d_in[9];
    float* out = (float*)d_out;

    uint32_t *dSbf, *dCbf;
    float *dH, *dW1, *dW2, *dW3;
    int *dCur;
    cudaGetSymbolAddress((void**)&dSbf, g_Sbf);
    cudaGetSymbolAddress((void**)&dH,   g_H);
    cudaGetSymbolAddress((void**)&dCbf, g_Cbf);
    cudaGetSymbolAddress((void**)&dW1,  g_W1c);
    cudaGetSymbolAddress((void**)&dW2,  g_W2c);
    cudaGetSymbolAddress((void**)&dW3,  g_W3c);
    cudaGetSymbolAddress((void**)&dCur, g_cursor);

    const int NB_SCAN = (NN + 1 + 1023) / 1024;
    const int EB = (EE + 255) / 256;

    // --- tf32 pre-rounding of weights (tiny) ---
    k_cvt_rna<<<(F0*F1/4 + 255) / 256, 256>>>(W1, dW1, F0*F1/4);
    k_cvt_rna<<<(F1*F2/4 + 255) / 256, 256>>>(W2, dW2, F1*F2/4);
    k_cvt_rna<<<(F2*F3/4 + 255) / 256, 256>>>(W3, dW3, F2*F3/4);

    // --- CSR build ---
    k_zero_int<<<(NN + 255) / 256, 256>>>(dCur, NN);
    k_hist<<<EB, 256>>>(erow);
    k_scan_block<<<NB_SCAN, 1024>>>(NN + 1);
    k_scan_spine<<<1, 128>>>(NB_SCAN);
    k_scan_add<<<NB_SCAN, 1024>>>(NN + 1);
    k_zero_int<<<(NN + 255) / 256, 256>>>(dCur, NN);
    k_scatter<<<EB, 256>>>(erow, ecol, eval);

    const int MB = (NN + 127) / 128;

    // --- layer 1: s1 = bf16(x @ W1); h1 = tf32(relu(spmm(s1) + b1)) ---
    k_gemm_tc<128,128,64,64,true, true><<<dim3(F1/128, MB), 128>>>(x,  dW1, dSbf, NN, F1, F0);
    k_spmm256_bf<<<NN, 128>>>(dSbf, b1, dH);

    // --- layer 2 ---
    k_gemm_tc<128,128,64,64,false,true><<<dim3(F2/128, MB), 128>>>(dH, dW2, dSbf, NN, F2, F1);
    k_spmm256_bf<<<NN, 128>>>(dSbf, b2, dH);

    // --- layer 3 + log_softmax ---
    k_gemm_tc<128,64,64,32,false,true><<<dim3(F3/64, MB), 128>>>(dH, dW3, dCbf, NN, F3, F2);
    k_spmm64_lsm_bf<<<NN/4, 128>>>(dCbf, b3, out);
}

// round 7
// speedup vs baseline: 3.3436x; 1.2617x over previous
#include <cuda_runtime.h>
#include <cuda_bf16.h>
#include <cuda_fp16.h>
#include <math.h>
#include <stdint.h>

// ---------------------------------------------------------------------------
// Problem constants
// ---------------------------------------------------------------------------
#define NN 100000
#define EE 3200000
#define F0 512
#define F1 256
#define F2 256
#define F3 64

// ---------------------------------------------------------------------------
// Scratch (__device__ globals; no allocations allowed)
// ---------------------------------------------------------------------------
__device__ uint32_t g_S8 [(size_t)NN * 64];    // fp8(e4m3) support, F=256 (25.6 MB)
__device__ float    g_H  [(size_t)NN * 256];   // fp32 (tf32-rounded) activations
__device__ uint32_t g_Cbf[(size_t)NN * 32];    // bf16x2 support, F=64
__device__ float    g_W1c[F0 * F1];
__device__ float    g_W2c[F1 * F2];
__device__ float    g_W3c[F2 * F3];
__device__ int      g_rowptr[NN + 1];
__device__ int      g_cursor[NN];
__device__ int2     g_edge[EE];                // packed (col, val-bits)
__device__ int      g_bsums[128];

__device__ __forceinline__ uint32_t f2tf32(float x) {
    uint32_t u;
    asm("cvt.rna.tf32.f32 %0, %1;" : "=r"(u) : "f"(x));
    return u;
}
// bf16x2 -> two fp32 (exact, pure ALU)
__device__ __forceinline__ float2 bf2x_to_f2(uint32_t u) {
    float2 f;
    f.x = __uint_as_float(u << 16);
    f.y = __uint_as_float(u & 0xffff0000u);
    return f;
}
// 2x e4m3 (packed u16) -> float2 via half2
__device__ __forceinline__ float2 fp8x2_to_f2(uint16_t p) {
    uint32_t h;
    asm("cvt.rn.f16x2.e4m3x2 %0, %1;" : "=r"(h) : "h"(p));
    return __half22float2(*(__half2*)&h);
}
__device__ __forceinline__ uint16_t f2_to_fp8x2(float lo, float hi) {
    uint16_t p;
    asm("cvt.rn.satfinite.e4m3x2.f32 %0, %1, %2;" : "=h"(p) : "f"(hi), "f"(lo));
    return p;  // low byte = lo
}

// ---------------------------------------------------------------------------
// tf32 rounding kernel (weights only — small)
// ---------------------------------------------------------------------------
__global__ void k_cvt_rna(const float* __restrict__ src, float* __restrict__ dst, int n4) {
    int i = blockIdx.x * blockDim.x + threadIdx.x;
    if (i < n4) {
        float4 v = ((const float4*)src)[i];
        v.x = __uint_as_float(f2tf32(v.x));
        v.y = __uint_as_float(f2tf32(v.y));
        v.z = __uint_as_float(f2tf32(v.z));
        v.w = __uint_as_float(f2tf32(v.w));
        ((float4*)dst)[i] = v;
    }
}

// ---------------------------------------------------------------------------
// CSR build: histogram -> exclusive scan -> scatter (packed records)
// ---------------------------------------------------------------------------
__global__ void k_zero_int(int* p, int n) {
    int i = blockIdx.x * blockDim.x + threadIdx.x;
    if (i < n) p[i] = 0;
}

__global__ void k_hist(const int* __restrict__ erow) {
    int e = blockIdx.x * blockDim.x + threadIdx.x;
    if (e < EE) atomicAdd(&g_cursor[erow[e]], 1);
}

__global__ void k_scan_block(int n) {
    int tid  = threadIdx.x;
    int i    = blockIdx.x * 1024 + tid;
    int v    = (i < NN) ? g_cursor[i] : 0;
    int lane = tid & 31, warp = tid >> 5;
    int x = v;
    #pragma unroll
    for (int o = 1; o < 32; o <<= 1) {
        int y = __shfl_up_sync(0xFFFFFFFFu, x, o);
        if (lane >= o) x += y;
    }
    __shared__ int wsum[32];
    if (lane == 31) wsum[warp] = x;
    __syncthreads();
    if (warp == 0) {
        int w = wsum[lane];
        #pragma unroll
        for (int o = 1; o < 32; o <<= 1) {
            int y = __shfl_up_sync(0xFFFFFFFFu, w, o);
            if (lane >= o) w += y;
        }
        wsum[lane] = w;
    }
    __syncthreads();
    int incl = x + (warp > 0 ? wsum[warp - 1] : 0);
    if (i < n) g_rowptr[i] = incl - v;
    if (tid == 1023) g_bsums[blockIdx.x] = incl;
}

__global__ void k_scan_spine(int nb) {
    int tid = threadIdx.x;
    int lane = tid & 31, warp = tid >> 5;
    int v = (tid < nb) ? g_bsums[tid] : 0;
    int x = v;
    #pragma unroll
    for (int o = 1; o < 32; o <<= 1) {
        int y = __shfl_up_sync(0xFFFFFFFFu, x, o);
        if (lane >= o) x += y;
    }
    __shared__ int ws[4];
    if (lane == 31) ws[warp] = x;
    __syncthreads();
    int off = 0;
    for (int w = 0; w < warp; w++) off += ws[w];
    if (tid < nb) g_bsums[tid] = (x + off) - v;
}

// adds block offsets; also seeds cursor = rowptr for the scatter pass
__global__ void k_scan_add(int n) {
    int i = blockIdx.x * 1024 + threadIdx.x;
    if (i < n) {
        int v = g_rowptr[i] + g_bsums[blockIdx.x];
        g_rowptr[i] = v;
        if (i < NN) g_cursor[i] = v;
    }
}

__global__ void k_scatter(const int* __restrict__ erow,
                          const int* __restrict__ ecol,
                          const float* __restrict__ eval) {
    int e = blockIdx.x * blockDim.x + threadIdx.x;
    if (e < EE) {
        int r = erow[e];
        int p = atomicAdd(&g_cursor[r], 1);
        int2 rec;
        rec.x = ecol[e];
        rec.y = __float_as_int(eval[e]);
        g_edge[p] = rec;
    }
}

// ---------------------------------------------------------------------------
// TF32 tensor-core GEMM: C[M,N] = A[M,K] @ W[K,N]
// mma.sync.m16n8k8.tf32, cp.async double-buffered, conflict-free padding.
// RND_A: cvt.rna.tf32 the A-fragments. OUT: 0=fp32, 1=bf16x2, 2=e4m3-packed.
// ---------------------------------------------------------------------------
template<int BM, int BN, int WM, int WN, bool RND_A, int OUT>
__global__ __launch_bounds__((BM/WM)*(BN/WN)*32) void k_gemm_tc(
    const float* __restrict__ A, const float* __restrict__ W,
    void* __restrict__ Cv, int M, int N, int K)
{
    constexpr int BK  = 16;
    constexpr int NWARP = (BM/WM)*(BN/WN);
    constexpr int NT  = NWARP * 32;
    constexpr int AST = BK + 4;
    constexpr int BST = BN + 8;
    constexpr int ACH = BM*BK/4/NT;
    constexpr int BCH = BK*BN/4/NT;
    constexpr int MT  = WM/16, NTL = WN/8;

    __shared__ float As[2][BM][AST];
    __shared__ float Bs[2][BK][BST];

    const int tid  = threadIdx.x;
    const int lane = tid & 31, wid = tid >> 5;
    const int wm   = (wid % (BM/WM)) * WM;
    const int wn   = (wid / (BM/WM)) * WN;
    const int m0   = blockIdx.y * BM, n0 = blockIdx.x * BN;

    float acc[MT][NTL][4];
    #pragma unroll
    for (int i = 0; i < MT; i++)
        #pragma unroll
        for (int j = 0; j < NTL; j++)
            #pragma unroll
            for (int q = 0; q < 4; q++) acc[i][j][q] = 0.f;

    const int T = K / BK;

    #define ISSUE(t, buf)                                                       \
    {                                                                           \
        int k0 = (t) * BK;                                                      \
        _Pragma("unroll")                                                       \
        for (int j = 0; j < ACH; j++) {                                         \
            int f = tid + j * NT;                                               \
            int m = f >> 2, c = (f & 3) << 2;                                   \
            int gm = m0 + m;                                                    \
            const float* src = A + (size_t)(gm < M ? gm : 0) * K + k0 + c;      \
            uint32_t dst = (uint32_t)__cvta_generic_to_shared(&As[buf][m][c]);  \
            int sz = (gm < M) ? 16 : 0;                                         \
            asm volatile("cp.async.ca.shared.global [%0], [%1], 16, %2;\n"      \
                         :: "r"(dst), "l"(src), "r"(sz));                       \
        }                                                                       \
        _Pragma("unroll")                                                       \
        for (int j = 0; j < BCH; j++) {                                         \
            int f = tid + j * NT;                                               \
            int k = f / (BN/4), c = (f % (BN/4)) << 2;                          \
            const float* src = W + (size_t)(k0 + k) * N + n0 + c;               \
            uint32_t dst = (uint32_t)__cvta_generic_to_shared(&Bs[buf][k][c]);  \
            asm volatile("cp.async.ca.shared.global [%0], [%1], 16;\n"          \
                         :: "r"(dst), "l"(src));                                \
        }                                                                       \
        asm volatile("cp.async.commit_group;\n");                               \
    }

    ISSUE(0, 0);
    ISSUE(1, 1);
    asm volatile("cp.async.wait_group 1;\n");
    __syncthreads();

    for (int t = 0; t < T; t++) {
        const int buf = t & 1;
        #pragma unroll
        for (int k8 = 0; k8 < 2; k8++) {
            const int kk   = k8 * 8 + (lane & 3);
            const int mrow = wm + (lane >> 2);
            uint32_t af[MT][4];
            #pragma unroll
            for (int mt = 0; mt < MT; mt++) {
                float a0 = As[buf][mrow + mt*16    ][kk    ];
                float a1 = As[buf][mrow + mt*16 + 8][kk    ];
                float a2 = As[buf][mrow + mt*16    ][kk + 4];
                float a3 = As[buf][mrow + mt*16 + 8][kk + 4];
                if (RND_A) {
                    af[mt][0] = f2tf32(a0); af[mt][1] = f2tf32(a1);
                    af[mt][2] = f2tf32(a2); af[mt][3] = f2tf32(a3);
                } else {
                    af[mt][0] = __float_as_uint(a0); af[mt][1] = __float_as_uint(a1);
                    af[mt][2] = __float_as_uint(a2); af[mt][3] = __float_as_uint(a3);
                }
            }
            #pragma unroll
            for (int nt = 0; nt < NTL; nt++) {
                const int ncol = wn + nt*8 + (lane >> 2);
                uint32_t b0 = __float_as_uint(Bs[buf][kk    ][ncol]);
                uint32_t b1 = __float_as_uint(Bs[buf][kk + 4][ncol]);
                #pragma unroll
                for (int mt = 0; mt < MT; mt++) {
                    asm volatile(
                        "mma.sync.aligned.m16n8k8.row.col.f32.tf32.tf32.f32 "
                        "{%0,%1,%2,%3},{%4,%5,%6,%7},{%8,%9},{%0,%1,%2,%3};\n"
                        : "+f"(acc[mt][nt][0]), "+f"(acc[mt][nt][1]),
                          "+f"(acc[mt][nt][2]), "+f"(acc[mt][nt][3])
                        : "r"(af[mt][0]), "r"(af[mt][1]),
                          "r"(af[mt][2]), "r"(af[mt][3]),
                          "r"(b0), "r"(b1));
                }
            }
        }
        __syncthreads();
        if (t + 2 < T) { ISSUE(t + 2, buf); }
        else           { asm volatile("cp.async.commit_group;\n"); }
        asm volatile("cp.async.wait_group 1;\n");
        __syncthreads();
    }
    #undef ISSUE

    // epilogue
    #pragma unroll
    for (int mt = 0; mt < MT; mt++) {
        int r0 = m0 + wm + mt*16 + (lane >> 2);
        #pragma unroll
        for (int nt = 0; nt < NTL; nt++) {
            int cc = n0 + wn + nt*8 + (lane & 3)*2;
            if (OUT == 2) {
                uint16_t* C8 = (uint16_t*)Cv;  // e4m3-packed, N/2 u16 per row
                if (r0 < M)
                    C8[(size_t)r0 * (N/2) + cc/2] =
                        f2_to_fp8x2(acc[mt][nt][0], acc[mt][nt][1]);
                if (r0 + 8 < M)
                    C8[(size_t)(r0 + 8) * (N/2) + cc/2] =
                        f2_to_fp8x2(acc[mt][nt][2], acc[mt][nt][3]);
            } else if (OUT == 1) {
                uint32_t* Cb = (uint32_t*)Cv;  // bf16x2-packed, N/2 per row
                if (r0 < M) {
                    __nv_bfloat162 p = __floats2bfloat162_rn(acc[mt][nt][0], acc[mt][nt][1]);
                    Cb[(size_t)r0 * (N/2) + cc/2] = *(uint32_t*)&p;
                }
                if (r0 + 8 < M) {
                    __nv_bfloat162 p = __floats2bfloat162_rn(acc[mt][nt][2], acc[mt][nt][3]);
                    Cb[(size_t)(r0 + 8) * (N/2) + cc/2] = *(uint32_t*)&p;
                }
            } else {
                float* C = (float*)Cv;
                if (r0 < M)
                    *(float2*)&C[(size_t)r0 * N + cc] =
                        make_float2(acc[mt][nt][0], acc[mt][nt][1]);
                if (r0 + 8 < M)
                    *(float2*)&C[(size_t)(r0 + 8) * N + cc] =
                        make_float2(acc[mt][nt][2], acc[mt][nt][3]);
            }
        }
    }
}

// ---------------------------------------------------------------------------
// SpMM F=256 over fp8 support: 2 rows per 128-block, 64 threads/row,
// each thread covers 4 features (one u32 gather / edge).
// out = tf32( relu( sum val*sup[col] + bias ) )  (fp32 accumulate)
// ---------------------------------------------------------------------------
__global__ __launch_bounds__(128) void k_spmm256_f8(
    const uint32_t* __restrict__ sup8, const float* __restrict__ bias,
    float* __restrict__ out)
{
    int t64 = threadIdx.x & 63;
    int row = blockIdx.x * 2 + (threadIdx.x >> 6);
    int s = g_rowptr[row], e = g_rowptr[row + 1];

    float a0 = 0.f, a1 = 0.f, a2 = 0.f, a3 = 0.f;
    int i = s;
    for (; i + 4 <= e; i += 4) {
        int2 r0 = g_edge[i],     r1 = g_edge[i + 1];
        int2 r2 = g_edge[i + 2], r3 = g_edge[i + 3];
        uint32_t u0 = sup8[(size_t)r0.x * 64 + t64];
        uint32_t u1 = sup8[(size_t)r1.x * 64 + t64];
        uint32_t u2 = sup8[(size_t)r2.x * 64 + t64];
        uint32_t u3 = sup8[(size_t)r3.x * 64 + t64];
        float v0 = __int_as_float(r0.y), v1 = __int_as_float(r1.y);
        float v2 = __int_as_float(r2.y), v3 = __int_as_float(r3.y);
        {
            float2 lo = fp8x2_to_f2((uint16_t)(u0 & 0xffff));
            float2 hi = fp8x2_to_f2((uint16_t)(u0 >> 16));
            a0 = fmaf(v0, lo.x, a0); a1 = fmaf(v0, lo.y, a1);
            a2 = fmaf(v0, hi.x, a2); a3 = fmaf(v0, hi.y, a3);
        }
        {
            float2 lo = fp8x2_to_f2((uint16_t)(u1 & 0xffff));
            float2 hi = fp8x2_to_f2((uint16_t)(u1 >> 16));
            a0 = fmaf(v1, lo.x, a0); a1 = fmaf(v1, lo.y, a1);
            a2 = fmaf(v1, hi.x, a2); a3 = fmaf(v1, hi.y, a3);
        }
        {
            float2 lo = fp8x2_to_f2((uint16_t)(u2 & 0xffff));
            float2 hi = fp8x2_to_f2((uint16_t)(u2 >> 16));
            a0 = fmaf(v2, lo.x, a0); a1 = fmaf(v2, lo.y, a1);
            a2 = fmaf(v2, hi.x, a2); a3 = fmaf(v2, hi.y, a3);
        }
        {
            float2 lo = fp8x2_to_f2((uint16_t)(u3 & 0xffff));
            float2 hi = fp8x2_to_f2((uint16_t)(u3 >> 16));
            a0 = fmaf(v3, lo.x, a0); a1 = fmaf(v3, lo.y, a1);
            a2 = fmaf(v3, hi.x, a2); a3 = fmaf(v3, hi.y, a3);
        }
    }
    for (; i < e; i++) {
        int2 r = g_edge[i];
        float v = __int_as_float(r.y);
        uint32_t u = sup8[(size_t)r.x * 64 + t64];
        float2 lo = fp8x2_to_f2((uint16_t)(u & 0xffff));
        float2 hi = fp8x2_to_f2((uint16_t)(u >> 16));
        a0 = fmaf(v, lo.x, a0); a1 = fmaf(v, lo.y, a1);
        a2 = fmaf(v, hi.x, a2); a3 = fmaf(v, hi.y, a3);
    }
    float4 b = *(const float4*)&bias[4 * t64];
    float4 o;
    o.x = __uint_as_float(f2tf32(fmaxf(a0 + b.x, 0.f)));
    o.y = __uint_as_float(f2tf32(fmaxf(a1 + b.y, 0.f)));
    o.z = __uint_as_float(f2tf32(fmaxf(a2 + b.z, 0.f)));
    o.w = __uint_as_float(f2tf32(fmaxf(a3 + b.w, 0.f)));
    *(float4*)&out[(size_t)row * 256 + 4 * t64] = o;
}

// ---------------------------------------------------------------------------
// SpMM F=64 (bf16 support) + bias + log_softmax. Warp per row, 4 rows/block.
// ---------------------------------------------------------------------------
__global__ __launch_bounds__(128) void k_spmm64_lsm_bf(
    const uint32_t* __restrict__ supu, const float* __restrict__ b3,
    float* __restrict__ out)
{
    int lane = threadIdx.x & 31;
    int row  = blockIdx.x * 4 + (threadIdx.x >> 5);

    int s = g_rowptr[row], e = g_rowptr[row + 1];

    float ax0 = 0.f, ay0 = 0.f, ax1 = 0.f, ay1 = 0.f;
    int i = s;
    for (; i + 4 <= e; i += 4) {
        int2 r0 = g_edge[i],     r1 = g_edge[i + 1];
        int2 r2 = g_edge[i + 2], r3 = g_edge[i + 3];
        float2 f0 = bf2x_to_f2(supu[(size_t)r0.x * 32 + lane]);
        float2 f1 = bf2x_to_f2(supu[(size_t)r1.x * 32 + lane]);
        float2 f2 = bf2x_to_f2(supu[(size_t)r2.x * 32 + lane]);
        float2 f3 = bf2x_to_f2(supu[(size_t)r3.x * 32 + lane]);
        float v0 = __int_as_float(r0.y), v1 = __int_as_float(r1.y);
        float v2 = __int_as_float(r2.y), v3 = __int_as_float(r3.y);
        ax0 = fmaf(v0, f0.x, ax0); ay0 = fmaf(v0, f0.y, ay0);
        ax1 = fmaf(v1, f1.x, ax1); ay1 = fmaf(v1, f1.y, ay1);
        ax0 = fmaf(v2, f2.x, ax0); ay0 = fmaf(v2, f2.y, ay0);
        ax1 = fmaf(v3, f3.x, ax1); ay1 = fmaf(v3, f3.y, ay1);
    }
    for (; i < e; i++) {
        int2 r = g_edge[i];
        float v = __int_as_float(r.y);
        float2 f = bf2x_to_f2(supu[(size_t)r.x * 32 + lane]);
        ax0 = fmaf(v, f.x, ax0); ay0 = fmaf(v, f.y, ay0);
    }
    float2 b = *(const float2*)&b3[2 * lane];
    float rx = ax0 + ax1 + b.x;
    float ry = ay0 + ay1 + b.y;

    // warp log-softmax over 64 values (2 per lane)
    float m = fmaxf(rx, ry);
    #pragma unroll
    for (int o = 16; o > 0; o >>= 1)
        m = fmaxf(m, __shfl_xor_sync(0xFFFFFFFFu, m, o));
    float sum = expf(rx - m) + expf(ry - m);
    #pragma unroll
    for (int o = 16; o > 0; o >>= 1)
        sum += __shfl_xor_sync(0xFFFFFFFFu, sum, o);
    float ls = m + logf(sum);

    float2 o2 = make_float2(rx - ls, ry - ls);
    *(float2*)&out[(size_t)row * 64 + 2 * lane] = o2;
}

// ---------------------------------------------------------------------------
// Launch
// ---------------------------------------------------------------------------
extern "C" void kernel_launch(void* const* d_in, const int* in_sizes, int n_in,
                              void* d_out, int out_size)
{
    const float* x    = (const float*)d_in[0];
    const int*   erow = (const int*)  d_in[1];
    const int*   ecol = (const int*)  d_in[2];
    const float* eval = (const float*)d_in[3];
    const float* W1   = (const float*)d_in[4];
    const float* b1   = (const float*)d_in[5];
    const float* W2   = (const float*)d_in[6];
    const float* b2   = (const float*)d_in[7];
    const float* W3   = (const float*)d_in[8];
    const float* b3   = (const float*)d_in[9];
    float* out = (float*)d_out;

    uint32_t *dS8, *dCbf;
    float *dH, *dW1, *dW2, *dW3;
    int *dCur;
    cudaGetSymbolAddress((void**)&dS8,  g_S8);
    cudaGetSymbolAddress((void**)&dH,   g_H);
    cudaGetSymbolAddress((void**)&dCbf, g_Cbf);
    cudaGetSymbolAddress((void**)&dW1,  g_W1c);
    cudaGetSymbolAddress((void**)&dW2,  g_W2c);
    cudaGetSymbolAddress((void**)&dW3,  g_W3c);
    cudaGetSymbolAddress((void**)&dCur, g_cursor);

    const int NB_SCAN = (NN + 1 + 1023) / 1024;
    const int EB = (EE + 255) / 256;

    // --- tf32 pre-rounding of weights (tiny) ---
    k_cvt_rna<<<(F0*F1/4 + 255) / 256, 256>>>(W1, dW1, F0*F1/4);
    k_cvt_rna<<<(F1*F2/4 + 255) / 256, 256>>>(W2, dW2, F1*F2/4);
    k_cvt_rna<<<(F2*F3/4 + 255) / 256, 256>>>(W3, dW3, F2*F3/4);

    // --- CSR build ---
    k_zero_int<<<(NN + 255) / 256, 256>>>(dCur, NN);
    k_hist<<<EB, 256>>>(erow);
    k_scan_block<<<NB_SCAN, 1024>>>(NN + 1);
    k_scan_spine<<<1, 128>>>(NB_SCAN);
    k_scan_add<<<NB_SCAN, 1024>>>(NN + 1);   // also seeds cursor = rowptr
    k_scatter<<<EB, 256>>>(erow, ecol, eval);

    const int MB = (NN + 127) / 128;

    // --- layer 1: s1 = fp8(x @ W1); h1 = tf32(relu(spmm(s1) + b1)) ---
    k_gemm_tc<128,128,64,64,true, 2><<<dim3(F1/128, MB), 128>>>(x,  dW1, dS8, NN, F1, F0);
    k_spmm256_f8<<<NN/2, 128>>>(dS8, b1, dH);

    // --- layer 2 ---
    k_gemm_tc<128,128,64,64,false,2><<<dim3(F2/128, MB), 128>>>(dH, dW2, dS8, NN, F2, F1);
    k_spmm256_f8<<<NN/2, 128>>>(dS8, b2, dH);

    // --- layer 3 + log_softmax ---
    k_gemm_tc<128,64,64,32,false,1><<<dim3(F3/64, MB), 128>>>(dH, dW3, dCbf, NN, F3, F2);
    k_spmm64_lsm_bf<<<NN/4, 128>>>(dCbf, b3, out);
}

// round 8
// speedup vs baseline: 3.8410x; 1.1488x over previous
#include <cuda_runtime.h>
#include <cuda_bf16.h>
#include <cuda_fp16.h>
#include <math.h>
#include <stdint.h>

// ---------------------------------------------------------------------------
// Problem constants
// ---------------------------------------------------------------------------
#define NN 100000
#define EE 3200000
#define F0 512
#define F1 256
#define F2 256
#define F3 64

// ---------------------------------------------------------------------------
// Scratch (__device__ globals; no allocations allowed)
// ---------------------------------------------------------------------------
__device__ uint16_t g_Xbf[(size_t)NN * F0];    // bf16 copy of x (102.4 MB)
__device__ uint32_t g_S8 [(size_t)NN * 64];    // fp8(e4m3) support, F=256 (25.6 MB)
__device__ uint32_t g_Hbf[(size_t)NN * 128];   // bf16x2 activations, F=256 (51.2 MB)
__device__ uint32_t g_Cbf[(size_t)NN * 32];    // bf16x2 support, F=64
__device__ uint16_t g_W1t[F1 * F0];            // Wt[N][K] bf16 (transposed)
__device__ uint16_t g_W2t[F2 * F1];
__device__ uint16_t g_W3t[F3 * F2];
__device__ int      g_rowptr[NN + 1];
__device__ int      g_cursor[NN];
__device__ int2     g_edge[EE];                // packed (col, val-bits)
__device__ int      g_bsums[128];

// bf16x2 -> two fp32 (exact, pure ALU)
__device__ __forceinline__ float2 bf2x_to_f2(uint32_t u) {
    float2 f;
    f.x = __uint_as_float(u << 16);
    f.y = __uint_as_float(u & 0xffff0000u);
    return f;
}
// 2x e4m3 (packed u16) -> float2 via half2
__device__ __forceinline__ float2 fp8x2_to_f2(uint16_t p) {
    uint32_t h;
    asm("cvt.rn.f16x2.e4m3x2 %0, %1;" : "=r"(h) : "h"(p));
    return __half22float2(*(__half2*)&h);
}
__device__ __forceinline__ uint16_t f2_to_fp8x2(float lo, float hi) {
    uint16_t p;
    asm("cvt.rn.satfinite.e4m3x2.f32 %0, %1, %2;" : "=h"(p) : "f"(hi), "f"(lo));
    return p;  // low byte = lo
}
__device__ __forceinline__ uint32_t f2_to_bf2x(float lo, float hi) {
    __nv_bfloat162 p = __floats2bfloat162_rn(lo, hi);
    return *(uint32_t*)&p;
}

// ---------------------------------------------------------------------------
// Conversions: x -> bf16 (same layout); W[K][N] -> Wt[N][K] bf16
// ---------------------------------------------------------------------------
__global__ void k_cvt_x_bf(const float* __restrict__ src, uint16_t* __restrict__ dst, int n8) {
    int i = blockIdx.x * blockDim.x + threadIdx.x;
    if (i < n8) {
        float4 v0 = ((const float4*)src)[2 * i];
        float4 v1 = ((const float4*)src)[2 * i + 1];
        uint4 o;
        o.x = f2_to_bf2x(v0.x, v0.y);
        o.y = f2_to_bf2x(v0.z, v0.w);
        o.z = f2_to_bf2x(v1.x, v1.y);
        o.w = f2_to_bf2x(v1.z, v1.w);
        ((uint4*)dst)[i] = o;
    }
}

__global__ void k_cvt_wt(const float* __restrict__ W, uint16_t* __restrict__ Wt, int K, int N) {
    int i = blockIdx.x * blockDim.x + threadIdx.x;
    if (i < K * N) {
        int k = i / N, n = i % N;
        __nv_bfloat16 b = __float2bfloat16(W[i]);
        Wt[(size_t)n * K + k] = *(uint16_t*)&b;
    }
}

// ---------------------------------------------------------------------------
// CSR build: histogram -> exclusive scan -> scatter (packed records)
// ---------------------------------------------------------------------------
__global__ void k_zero_int(int* p, int n) {
    int i = blockIdx.x * blockDim.x + threadIdx.x;
    if (i < n) p[i] = 0;
}

__global__ void k_hist(const int* __restrict__ erow) {
    int e = blockIdx.x * blockDim.x + threadIdx.x;
    if (e < EE) atomicAdd(&g_cursor[erow[e]], 1);
}

__global__ void k_scan_block(int n) {
    int tid  = threadIdx.x;
    int i    = blockIdx.x * 1024 + tid;
    int v    = (i < NN) ? g_cursor[i] : 0;
    int lane = tid & 31, warp = tid >> 5;
    int x = v;
    #pragma unroll
    for (int o = 1; o < 32; o <<= 1) {
        int y = __shfl_up_sync(0xFFFFFFFFu, x, o);
        if (lane >= o) x += y;
    }
    __shared__ int wsum[32];
    if (lane == 31) wsum[warp] = x;
    __syncthreads();
    if (warp == 0) {
        int w = wsum[lane];
        #pragma unroll
        for (int o = 1; o < 32; o <<= 1) {
            int y = __shfl_up_sync(0xFFFFFFFFu, w, o);
            if (lane >= o) w += y;
        }
        wsum[lane] = w;
    }
    __syncthreads();
    int incl = x + (warp > 0 ? wsum[warp - 1] : 0);
    if (i < n) g_rowptr[i] = incl - v;
    if (tid == 1023) g_bsums[blockIdx.x] = incl;
}

__global__ void k_scan_spine(int nb) {
    int tid = threadIdx.x;
    int lane = tid & 31, warp = tid >> 5;
    int v = (tid < nb) ? g_bsums[tid] : 0;
    int x = v;
    #pragma unroll
    for (int o = 1; o < 32; o <<= 1) {
        int y = __shfl_up_sync(0xFFFFFFFFu, x, o);
        if (lane >= o) x += y;
    }
    __shared__ int ws[4];
    if (lane == 31) ws[warp] = x;
    __syncthreads();
    int off = 0;
    for (int w = 0; w < warp; w++) off += ws[w];
    if (tid < nb) g_bsums[tid] = (x + off) - v;
}

// adds block offsets; also seeds cursor = rowptr for the scatter pass
__global__ void k_scan_add(int n) {
    int i = blockIdx.x * 1024 + threadIdx.x;
    if (i < n) {
        int v = g_rowptr[i] + g_bsums[blockIdx.x];
        g_rowptr[i] = v;
        if (i < NN) g_cursor[i] = v;
    }
}

__global__ void k_scatter(const int* __restrict__ erow,
                          const int* __restrict__ ecol,
                          const float* __restrict__ eval) {
    int e = blockIdx.x * blockDim.x + threadIdx.x;
    if (e < EE) {
        int r = erow[e];
        int p = atomicAdd(&g_cursor[r], 1);
        int2 rec;
        rec.x = ecol[e];
        rec.y = __float_as_int(eval[e]);
        g_edge[p] = rec;
    }
}

// ---------------------------------------------------------------------------
// BF16 tensor-core GEMM: C[M,N] = A[M,K] @ Wt[N,K]^T
// mma.sync.m16n8k16.bf16, cp.async double-buffered, 80B-stride (conflict-free).
// OUT: 1 = bf16x2 packed, 2 = e4m3 packed.
// ---------------------------------------------------------------------------
template<int BM, int BN, int WM, int WN, int OUT>
__global__ __launch_bounds__((BM/WM)*(BN/WN)*32) void k_gemm_bf(
    const uint16_t* __restrict__ A, const uint16_t* __restrict__ Wt,
    void* __restrict__ Cv, int M, int N, int K)
{
    constexpr int BK  = 32;
    constexpr int NWARP = (BM/WM)*(BN/WN);
    constexpr int NT  = NWARP * 32;
    constexpr int ST  = BK + 8;            // 40 bf16 = 80 B row stride
    constexpr int ACH = BM*BK/8/NT;        // 16B chunks per thread (A tile)
    constexpr int BCH = BN*BK/8/NT;
    constexpr int MT  = WM/16, NTL = WN/8;

    __shared__ uint16_t As[2][BM][ST];
    __shared__ uint16_t Bs[2][BN][ST];

    const int tid  = threadIdx.x;
    const int lane = tid & 31, wid = tid >> 5;
    const int wm   = (wid % (BM/WM)) * WM;
    const int wn   = (wid / (BM/WM)) * WN;
    const int m0   = blockIdx.y * BM, n0 = blockIdx.x * BN;

    float acc[MT][NTL][4];
    #pragma unroll
    for (int i = 0; i < MT; i++)
        #pragma unroll
        for (int j = 0; j < NTL; j++)
            #pragma unroll
            for (int q = 0; q < 4; q++) acc[i][j][q] = 0.f;

    const int T = K / BK;

    #define ISSUE(t, buf)                                                       \
    {                                                                           \
        int k0 = (t) * BK;                                                      \
        _Pragma("unroll")                                                       \
        for (int j = 0; j < ACH; j++) {                                         \
            int f = tid + j * NT;                                               \
            int m = f >> 2, c = (f & 3) << 3;                                   \
            int gm = m0 + m;                                                    \
            const uint16_t* src = A + (size_t)(gm < M ? gm : 0) * K + k0 + c;   \
            uint32_t dst = (uint32_t)__cvta_generic_to_shared(&As[buf][m][c]);  \
            int sz = (gm < M) ? 16 : 0;                                         \
            asm volatile("cp.async.ca.shared.global [%0], [%1], 16, %2;\n"      \
                         :: "r"(dst), "l"(src), "r"(sz));                       \
        }                                                                       \
        _Pragma("unroll")                                                       \
        for (int j = 0; j < BCH; j++) {                                         \
            int f = tid + j * NT;                                               \
            int n = f >> 2, c = (f & 3) << 3;                                   \
            const uint16_t* src = Wt + (size_t)(n0 + n) * K + k0 + c;           \
            uint32_t dst = (uint32_t)__cvta_generic_to_shared(&Bs[buf][n][c]);  \
            asm volatile("cp.async.ca.shared.global [%0], [%1], 16;\n"          \
                         :: "r"(dst), "l"(src));                                \
        }                                                                       \
        asm volatile("cp.async.commit_group;\n");                               \
    }

    ISSUE(0, 0);
    ISSUE(1, 1);
    asm volatile("cp.async.wait_group 1;\n");
    __syncthreads();

    const int r  = lane >> 2;
    const int c0 = (lane & 3) * 2;

    for (int t = 0; t < T; t++) {
        const int buf = t & 1;
        #pragma unroll
        for (int s = 0; s < 2; s++) {           // two k16 steps per BK=32
            const int kb = s * 16;
            uint32_t af[MT][4];
            #pragma unroll
            for (int mt = 0; mt < MT; mt++) {
                const uint16_t* pr0 = &As[buf][wm + mt*16 + r    ][kb + c0];
                const uint16_t* pr8 = &As[buf][wm + mt*16 + r + 8][kb + c0];
                af[mt][0] = *(const uint32_t*)pr0;
                af[mt][1] = *(const uint32_t*)pr8;
                af[mt][2] = *(const uint32_t*)(pr0 + 8);
                af[mt][3] = *(const uint32_t*)(pr8 + 8);
            }
            #pragma unroll
            for (int nt = 0; nt < NTL; nt++) {
                const uint16_t* pb = &Bs[buf][wn + nt*8 + r][kb + c0];
                uint32_t b0 = *(const uint32_t*)pb;
                uint32_t b1 = *(const uint32_t*)(pb + 8);
                #pragma unroll
                for (int mt = 0; mt < MT; mt++) {
                    asm volatile(
                        "mma.sync.aligned.m16n8k16.row.col.f32.bf16.bf16.f32 "
                        "{%0,%1,%2,%3},{%4,%5,%6,%7},{%8,%9},{%0,%1,%2,%3};\n"
                        : "+f"(acc[mt][nt][0]), "+f"(acc[mt][nt][1]),
                          "+f"(acc[mt][nt][2]), "+f"(acc[mt][nt][3])
                        : "r"(af[mt][0]), "r"(af[mt][1]),
                          "r"(af[mt][2]), "r"(af[mt][3]),
                          "r"(b0), "r"(b1));
                }
            }
        }
        __syncthreads();
        if (t + 2 < T) { ISSUE(t + 2, buf); }
        else           { asm volatile("cp.async.commit_group;\n"); }
        asm volatile("cp.async.wait_group 1;\n");
        __syncthreads();
    }
    #undef ISSUE

    // epilogue: C layout per mma m16n8: rows r/r+8, cols 2q,2q+1
    #pragma unroll
    for (int mt = 0; mt < MT; mt++) {
        int r0 = m0 + wm + mt*16 + r;
        #pragma unroll
        for (int nt = 0; nt < NTL; nt++) {
            int cc = n0 + wn + nt*8 + c0;
            if (OUT == 2) {
                uint16_t* C8 = (uint16_t*)Cv;  // e4m3-packed, N/2 u16 per row
                if (r0 < M)
                    C8[(size_t)r0 * (N/2) + cc/2] =
                        f2_to_fp8x2(acc[mt][nt][0], acc[mt][nt][1]);
                if (r0 + 8 < M)
                    C8[(size_t)(r0 + 8) * (N/2) + cc/2] =
                        f2_to_fp8x2(acc[mt][nt][2], acc[mt][nt][3]);
            } else {
                uint32_t* Cb = (uint32_t*)Cv;  // bf16x2-packed, N/2 u32 per row
                if (r0 < M)
                    Cb[(size_t)r0 * (N/2) + cc/2] =
                        f2_to_bf2x(acc[mt][nt][0], acc[mt][nt][1]);
                if (r0 + 8 < M)
                    Cb[(size_t)(r0 + 8) * (N/2) + cc/2] =
                        f2_to_bf2x(acc[mt][nt][2], acc[mt][nt][3]);
            }
        }
    }
}

// ---------------------------------------------------------------------------
// SpMM F=256 over fp8 support: 2 rows per 128-block, 64 threads/row,
// each thread covers 4 features (one u32 gather / edge).
// out = bf16( relu( sum val*sup[col] + bias ) )  (fp32 accumulate)
// ---------------------------------------------------------------------------
__global__ __launch_bounds__(128) void k_spmm256_f8(
    const uint32_t* __restrict__ sup8, const float* __restrict__ bias,
    uint32_t* __restrict__ out)
{
    int t64 = threadIdx.x & 63;
    int row = blockIdx.x * 2 + (threadIdx.x >> 6);
    int s = g_rowptr[row], e = g_rowptr[row + 1];

    float a0 = 0.f, a1 = 0.f, a2 = 0.f, a3 = 0.f;
    int i = s;
    for (; i + 4 <= e; i += 4) {
        int2 r0 = g_edge[i],     r1 = g_edge[i + 1];
        int2 r2 = g_edge[i + 2], r3 = g_edge[i + 3];
        uint32_t u0 = sup8[(size_t)r0.x * 64 + t64];
        uint32_t u1 = sup8[(size_t)r1.x * 64 + t64];
        uint32_t u2 = sup8[(size_t)r2.x * 64 + t64];
        uint32_t u3 = sup8[(size_t)r3.x * 64 + t64];
        float v0 = __int_as_float(r0.y), v1 = __int_as_float(r1.y);
        float v2 = __int_as_float(r2.y), v3 = __int_as_float(r3.y);
        {
            float2 lo = fp8x2_to_f2((uint16_t)(u0 & 0xffff));
            float2 hi = fp8x2_to_f2((uint16_t)(u0 >> 16));
            a0 = fmaf(v0, lo.x, a0); a1 = fmaf(v0, lo.y, a1);
            a2 = fmaf(v0, hi.x, a2); a3 = fmaf(v0, hi.y, a3);
        }
        {
            float2 lo = fp8x2_to_f2((uint16_t)(u1 & 0xffff));
            float2 hi = fp8x2_to_f2((uint16_t)(u1 >> 16));
            a0 = fmaf(v1, lo.x, a0); a1 = fmaf(v1, lo.y, a1);
            a2 = fmaf(v1, hi.x, a2); a3 = fmaf(v1, hi.y, a3);
        }
        {
            float2 lo = fp8x2_to_f2((uint16_t)(u2 & 0xffff));
            float2 hi = fp8x2_to_f2((uint16_t)(u2 >> 16));
            a0 = fmaf(v2, lo.x, a0); a1 = fmaf(v2, lo.y, a1);
            a2 = fmaf(v2, hi.x, a2); a3 = fmaf(v2, hi.y, a3);
        }
        {
            float2 lo = fp8x2_to_f2((uint16_t)(u3 & 0xffff));
            float2 hi = fp8x2_to_f2((uint16_t)(u3 >> 16));
            a0 = fmaf(v3, lo.x, a0); a1 = fmaf(v3, lo.y, a1);
            a2 = fmaf(v3, hi.x, a2); a3 = fmaf(v3, hi.y, a3);
        }
    }
    for (; i < e; i++) {
        int2 r = g_edge[i];
        float v = __int_as_float(r.y);
        uint32_t u = sup8[(size_t)r.x * 64 + t64];
        float2 lo = fp8x2_to_f2((uint16_t)(u & 0xffff));
        float2 hi = fp8x2_to_f2((uint16_t)(u >> 16));
        a0 = fmaf(v, lo.x, a0); a1 = fmaf(v, lo.y, a1);
        a2 = fmaf(v, hi.x, a2); a3 = fmaf(v, hi.y, a3);
    }
    float4 b = *(const float4*)&bias[4 * t64];
    uint2 o;
    o.x = f2_to_bf2x(fmaxf(a0 + b.x, 0.f), fmaxf(a1 + b.y, 0.f));
    o.y = f2_to_bf2x(fmaxf(a2 + b.z, 0.f), fmaxf(a3 + b.w, 0.f));
    *(uint2*)&out[(size_t)row * 128 + 2 * t64] = o;
}

// ---------------------------------------------------------------------------
// SpMM F=64 (bf16 support) + bias + log_softmax. Warp per row, 4 rows/block.
// ---------------------------------------------------------------------------
__global__ __launch_bounds__(128) void k_spmm64_lsm_bf(
    const uint32_t* __restrict__ supu, const float* __restrict__ b3,
    float* __restrict__ out)
{
    int lane = threadIdx.x & 31;
    int row  = blockIdx.x * 4 + (threadIdx.x >> 5);

    int s = g_rowptr[row], e = g_rowptr[row + 1];

    float ax0 = 0.f, ay0 = 0.f, ax1 = 0.f, ay1 = 0.f;
    int i = s;
    for (; i + 4 <= e; i += 4) {
        int2 r0 = g_edge[i],     r1 = g_edge[i + 1];
        int2 r2 = g_edge[i + 2], r3 = g_edge[i + 3];
        float2 f0 = bf2x_to_f2(supu[(size_t)r0.x * 32 + lane]);
        float2 f1 = bf2x_to_f2(supu[(size_t)r1.x * 32 + lane]);
        float2 f2 = bf2x_to_f2(supu[(size_t)r2.x * 32 + lane]);
        float2 f3 = bf2x_to_f2(supu[(size_t)r3.x * 32 + lane]);
        float v0 = __int_as_float(r0.y), v1 = __int_as_float(r1.y);
        float v2 = __int_as_float(r2.y), v3 = __int_as_float(r3.y);
        ax0 = fmaf(v0, f0.x, ax0); ay0 = fmaf(v0, f0.y, ay0);
        ax1 = fmaf(v1, f1.x, ax1); ay1 = fmaf(v1, f1.y, ay1);
        ax0 = fmaf(v2, f2.x, ax0); ay0 = fmaf(v2, f2.y, ay0);
        ax1 = fmaf(v3, f3.x, ax1); ay1 = fmaf(v3, f3.y, ay1);
    }
    for (; i < e; i++) {
        int2 r = g_edge[i];
        float v = __int_as_float(r.y);
        float2 f = bf2x_to_f2(supu[(size_t)r.x * 32 + lane]);
        ax0 = fmaf(v, f.x, ax0); ay0 = fmaf(v, f.y, ay0);
    }
    float2 b = *(const float2*)&b3[2 * lane];
    float rx = ax0 + ax1 + b.x;
    float ry = ay0 + ay1 + b.y;

    // warp log-softmax over 64 values (2 per lane)
    float m = fmaxf(rx, ry);
    #pragma unroll
    for (int o = 16; o > 0; o >>= 1)
        m = fmaxf(m, __shfl_xor_sync(0xFFFFFFFFu, m, o));
    float sum = expf(rx - m) + expf(ry - m);
    #pragma unroll
    for (int o = 16; o > 0; o >>= 1)
        sum += __shfl_xor_sync(0xFFFFFFFFu, sum, o);
    float ls = m + logf(sum);

    float2 o2 = make_float2(rx - ls, ry - ls);
    *(float2*)&out[(size_t)row * 64 + 2 * lane] = o2;
}

// ---------------------------------------------------------------------------
// Launch
// ---------------------------------------------------------------------------
extern "C" void kernel_launch(void* const* d_in, const int* in_sizes, int n_in,
                              void* d_out, int out_size)
{
    const float* x    = (const float*)d_in[0];
    const int*   erow = (const int*)  d_in[1];
    const int*   ecol = (const int*)  d_in[2];
    const float* eval = (const float*)d_in[3];
    const float* W1   = (const float*)d_in[4];
    const float* b1   = (const float*)d_in[5];
    const float* W2   = (const float*)d_in[6];
    const float* b2   = (const float*)d_in[7];
    const float* W3   = (const float*)d_in[8];
    const float* b3   = (const float*)d_in[9];
    float* out = (float*)d_out;

    uint16_t *dXbf, *dW1t, *dW2t, *dW3t;
    uint32_t *dS8, *dHbf, *dCbf;
    int *dCur;
    cudaGetSymbolAddress((void**)&dXbf, g_Xbf);
    cudaGetSymbolAddress((void**)&dS8,  g_S8);
    cudaGetSymbolAddress((void**)&dHbf, g_Hbf);
    cudaGetSymbolAddress((void**)&dCbf, g_Cbf);
    cudaGetSymbolAddress((void**)&dW1t, g_W1t);
    cudaGetSymbolAddress((void**)&dW2t, g_W2t);
    cudaGetSymbolAddress((void**)&dW3t, g_W3t);
    cudaGetSymbolAddress((void**)&dCur, g_cursor);

    const int NB_SCAN = (NN + 1 + 1023) / 1024;
    const int EB = (EE + 255) / 256;

    // --- bf16 conversions: x (big) and transposed weights (tiny) ---
    {
        int n8 = NN * F0 / 8;
        k_cvt_x_bf<<<(n8 + 255) / 256, 256>>>(x, dXbf, n8);
        k_cvt_wt<<<(F0*F1 + 255) / 256, 256>>>(W1, dW1t, F0, F1);
        k_cvt_wt<<<(F1*F2 + 255) / 256, 256>>>(W2, dW2t, F1, F2);
        k_cvt_wt<<<(F2*F3 + 255) / 256, 256>>>(W3, dW3t, F2, F3);
    }

    // --- CSR build ---
    k_zero_int<<<(NN + 255) / 256, 256>>>(dCur, NN);
    k_hist<<<EB, 256>>>(erow);
    k_scan_block<<<NB_SCAN, 1024>>>(NN + 1);
    k_scan_spine<<<1, 128>>>(NB_SCAN);
    k_scan_add<<<NB_SCAN, 1024>>>(NN + 1);   // also seeds cursor = rowptr
    k_scatter<<<EB, 256>>>(erow, ecol, eval);

    const int MB = (NN + 127) / 128;

    // --- layer 1: s1 = fp8(x @ W1); h1 = bf16(relu(spmm(s1) + b1)) ---
    k_gemm_bf<128,128,64,64,2><<<dim3(F1/128, MB), 128>>>(dXbf, dW1t, dS8, NN, F1, F0);
    k_spmm256_f8<<<NN/2, 128>>>(dS8, b1, dHbf);

    // --- layer 2 ---
    k_gemm_bf<128,128,64,64,2><<<dim3(F2/128, MB), 128>>>((const uint16_t*)dHbf, dW2t, dS8, NN, F2, F1);
    k_spmm256_f8<<<NN/2, 128>>>(dS8, b2, dHbf);

    // --- layer 3 + log_softmax ---
    k_gemm_bf<128,64,64,32,1><<<dim3(F3/64, MB), 128>>>((const uint16_t*)dHbf, dW3t, dCbf, NN, F3, F2);
    k_spmm64_lsm_bf<<<NN/4, 128>>>(dCbf, b3, out);
}

// round 9
// speedup vs baseline: 3.9302x; 1.0232x over previous
#include <cuda_runtime.h>
#include <cuda_bf16.h>
#include <cuda_fp16.h>
#include <math.h>
#include <stdint.h>

// ---------------------------------------------------------------------------
// Problem constants
// ---------------------------------------------------------------------------
#define NN 100000
#define EE 3200000
#define F0 512
#define F1 256
#define F2 256
#define F3 64

// ---------------------------------------------------------------------------
// Scratch (__device__ globals; no allocations allowed)
// ---------------------------------------------------------------------------
__device__ uint16_t g_Xbf[(size_t)NN * F0];    // bf16 copy of x (102.4 MB)
__device__ uint32_t g_S8 [(size_t)NN * 64];    // fp8(e4m3) support, F=256 (25.6 MB)
__device__ uint32_t g_Hbf[(size_t)NN * 128];   // bf16x2 activations, F=256 (51.2 MB)
__device__ uint32_t g_Cbf[(size_t)NN * 32];    // bf16x2 support, F=64
__device__ uint16_t g_W1t[F1 * F0];            // Wt[N][K] bf16 (transposed)
__device__ uint16_t g_W2t[F2 * F1];
__device__ uint16_t g_W3t[F3 * F2];
__device__ int      g_rowptr[NN + 1];
__device__ int      g_cursor[NN];
__device__ int2     g_edge[EE];                // packed (col, val-bits)
__device__ int      g_bsums[128];

// bf16x2 -> two fp32 (exact, pure ALU)
__device__ __forceinline__ float2 bf2x_to_f2(uint32_t u) {
    float2 f;
    f.x = __uint_as_float(u << 16);
    f.y = __uint_as_float(u & 0xffff0000u);
    return f;
}
// 2x e4m3 (packed u16) -> float2 via half2
__device__ __forceinline__ float2 fp8x2_to_f2(uint16_t p) {
    uint32_t h;
    asm("cvt.rn.f16x2.e4m3x2 %0, %1;" : "=r"(h) : "h"(p));
    return __half22float2(*(__half2*)&h);
}
__device__ __forceinline__ uint16_t f2_to_fp8x2(float lo, float hi) {
    uint16_t p;
    asm("cvt.rn.satfinite.e4m3x2.f32 %0, %1, %2;" : "=h"(p) : "f"(hi), "f"(lo));
    return p;  // low byte = lo
}
__device__ __forceinline__ uint32_t f2_to_bf2x(float lo, float hi) {
    __nv_bfloat162 p = __floats2bfloat162_rn(lo, hi);
    return *(uint32_t*)&p;
}

// ---------------------------------------------------------------------------
// Conversions: x -> bf16 (same layout); W[K][N] -> Wt[N][K] bf16
// ---------------------------------------------------------------------------
__global__ void k_cvt_x_bf(const float* __restrict__ src, uint16_t* __restrict__ dst, int n8) {
    int i = blockIdx.x * blockDim.x + threadIdx.x;
    if (i < n8) {
        float4 v0 = ((const float4*)src)[2 * i];
        float4 v1 = ((const float4*)src)[2 * i + 1];
        uint4 o;
        o.x = f2_to_bf2x(v0.x, v0.y);
        o.y = f2_to_bf2x(v0.z, v0.w);
        o.z = f2_to_bf2x(v1.x, v1.y);
        o.w = f2_to_bf2x(v1.z, v1.w);
        ((uint4*)dst)[i] = o;
    }
}

__global__ void k_cvt_wt(const float* __restrict__ W, uint16_t* __restrict__ Wt, int K, int N) {
    int i = blockIdx.x * blockDim.x + threadIdx.x;
    if (i < K * N) {
        int k = i / N, n = i % N;
        __nv_bfloat16 b = __float2bfloat16(W[i]);
        Wt[(size_t)n * K + k] = *(uint16_t*)&b;
    }
}

// ---------------------------------------------------------------------------
// CSR build: histogram -> exclusive scan -> scatter (packed records)
// ---------------------------------------------------------------------------
__global__ void k_zero_int(int* p, int n) {
    int i = blockIdx.x * blockDim.x + threadIdx.x;
    if (i < n) p[i] = 0;
}

__global__ void k_hist(const int* __restrict__ erow) {
    int e = blockIdx.x * blockDim.x + threadIdx.x;
    if (e < EE) atomicAdd(&g_cursor[erow[e]], 1);
}

__global__ void k_scan_block(int n) {
    int tid  = threadIdx.x;
    int i    = blockIdx.x * 1024 + tid;
    int v    = (i < NN) ? g_cursor[i] : 0;
    int lane = tid & 31, warp = tid >> 5;
    int x = v;
    #pragma unroll
    for (int o = 1; o < 32; o <<= 1) {
        int y = __shfl_up_sync(0xFFFFFFFFu, x, o);
        if (lane >= o) x += y;
    }
    __shared__ int wsum[32];
    if (lane == 31) wsum[warp] = x;
    __syncthreads();
    if (warp == 0) {
        int w = wsum[lane];
        #pragma unroll
        for (int o = 1; o < 32; o <<= 1) {
            int y = __shfl_up_sync(0xFFFFFFFFu, w, o);
            if (lane >= o) w += y;
        }
        wsum[lane] = w;
    }
    __syncthreads();
    int incl = x + (warp > 0 ? wsum[warp - 1] : 0);
    if (i < n) g_rowptr[i] = incl - v;
    if (tid == 1023) g_bsums[blockIdx.x] = incl;
}

__global__ void k_scan_spine(int nb) {
    int tid = threadIdx.x;
    int lane = tid & 31, warp = tid >> 5;
    int v = (tid < nb) ? g_bsums[tid] : 0;
    int x = v;
    #pragma unroll
    for (int o = 1; o < 32; o <<= 1) {
        int y = __shfl_up_sync(0xFFFFFFFFu, x, o);
        if (lane >= o) x += y;
    }
    __shared__ int ws[4];
    if (lane == 31) ws[warp] = x;
    __syncthreads();
    int off = 0;
    for (int w = 0; w < warp; w++) off += ws[w];
    if (tid < nb) g_bsums[tid] = (x + off) - v;
}

// adds block offsets; also seeds cursor = rowptr for the scatter pass
__global__ void k_scan_add(int n) {
    int i = blockIdx.x * 1024 + threadIdx.x;
    if (i < n) {
        int v = g_rowptr[i] + g_bsums[blockIdx.x];
        g_rowptr[i] = v;
        if (i < NN) g_cursor[i] = v;
    }
}

__global__ void k_scatter(const int* __restrict__ erow,
                          const int* __restrict__ ecol,
                          const float* __restrict__ eval) {
    int e = blockIdx.x * blockDim.x + threadIdx.x;
    if (e < EE) {
        int r = erow[e];
        int p = atomicAdd(&g_cursor[r], 1);
        int2 rec;
        rec.x = ecol[e];
        rec.y = __float_as_int(eval[e]);
        g_edge[p] = rec;
    }
}

// ---------------------------------------------------------------------------
// BF16 tensor-core GEMM: C[M,N] = A[M,K] @ Wt[N,K]^T
// mma.sync.m16n8k16.bf16, cp.async double-buffered, 80B-stride (conflict-free).
// OUT: 1 = bf16x2 packed, 2 = e4m3 packed.
// ---------------------------------------------------------------------------
template<int BM, int BN, int WM, int WN, int OUT>
__global__ __launch_bounds__((BM/WM)*(BN/WN)*32) void k_gemm_bf(
    const uint16_t* __restrict__ A, const uint16_t* __restrict__ Wt,
    void* __restrict__ Cv, int M, int N, int K)
{
    constexpr int BK  = 32;
    constexpr int NWARP = (BM/WM)*(BN/WN);
    constexpr int NT  = NWARP * 32;
    constexpr int ST  = BK + 8;            // 40 bf16 = 80 B row stride
    constexpr int ACH = BM*BK/8/NT;        // 16B chunks per thread (A tile)
    constexpr int BCH = BN*BK/8/NT;
    constexpr int MT  = WM/16, NTL = WN/8;

    __shared__ uint16_t As[2][BM][ST];
    __shared__ uint16_t Bs[2][BN][ST];

    const int tid  = threadIdx.x;
    const int lane = tid & 31, wid = tid >> 5;
    const int wm   = (wid % (BM/WM)) * WM;
    const int wn   = (wid / (BM/WM)) * WN;
    const int m0   = blockIdx.y * BM, n0 = blockIdx.x * BN;

    float acc[MT][NTL][4];
    #pragma unroll
    for (int i = 0; i < MT; i++)
        #pragma unroll
        for (int j = 0; j < NTL; j++)
            #pragma unroll
            for (int q = 0; q < 4; q++) acc[i][j][q] = 0.f;

    const int T = K / BK;

    #define ISSUE(t, buf)                                                       \
    {                                                                           \
        int k0 = (t) * BK;                                                      \
        _Pragma("unroll")                                                       \
        for (int j = 0; j < ACH; j++) {                                         \
            int f = tid + j * NT;                                               \
            int m = f >> 2, c = (f & 3) << 3;                                   \
            int gm = m0 + m;                                                    \
            const uint16_t* src = A + (size_t)(gm < M ? gm : 0) * K + k0 + c;   \
            uint32_t dst = (uint32_t)__cvta_generic_to_shared(&As[buf][m][c]);  \
            int sz = (gm < M) ? 16 : 0;                                         \
            asm volatile("cp.async.ca.shared.global [%0], [%1], 16, %2;\n"      \
                         :: "r"(dst), "l"(src), "r"(sz));                       \
        }                                                                       \
        _Pragma("unroll")                                                       \
        for (int j = 0; j < BCH; j++) {                                         \
            int f = tid + j * NT;                                               \
            int n = f >> 2, c = (f & 3) << 3;                                   \
            const uint16_t* src = Wt + (size_t)(n0 + n) * K + k0 + c;           \
            uint32_t dst = (uint32_t)__cvta_generic_to_shared(&Bs[buf][n][c]);  \
            asm volatile("cp.async.ca.shared.global [%0], [%1], 16;\n"          \
                         :: "r"(dst), "l"(src));                                \
        }                                                                       \
        asm volatile("cp.async.commit_group;\n");                               \
    }

    ISSUE(0, 0);
    ISSUE(1, 1);
    asm volatile("cp.async.wait_group 1;\n");
    __syncthreads();

    const int r  = lane >> 2;
    const int c0 = (lane & 3) * 2;

    for (int t = 0; t < T; t++) {
        const int buf = t & 1;
        #pragma unroll
        for (int s = 0; s < 2; s++) {           // two k16 steps per BK=32
            const int kb = s * 16;
            uint32_t af[MT][4];
            #pragma unroll
            for (int mt = 0; mt < MT; mt++) {
                const uint16_t* pr0 = &As[buf][wm + mt*16 + r    ][kb + c0];
                const uint16_t* pr8 = &As[buf][wm + mt*16 + r + 8][kb + c0];
                af[mt][0] = *(const uint32_t*)pr0;
                af[mt][1] = *(const uint32_t*)pr8;
                af[mt][2] = *(const uint32_t*)(pr0 + 8);
                af[mt][3] = *(const uint32_t*)(pr8 + 8);
            }
            #pragma unroll
            for (int nt = 0; nt < NTL; nt++) {
                const uint16_t* pb = &Bs[buf][wn + nt*8 + r][kb + c0];
                uint32_t b0 = *(const uint32_t*)pb;
                uint32_t b1 = *(const uint32_t*)(pb + 8);
                #pragma unroll
                for (int mt = 0; mt < MT; mt++) {
                    asm volatile(
                        "mma.sync.aligned.m16n8k16.row.col.f32.bf16.bf16.f32 "
                        "{%0,%1,%2,%3},{%4,%5,%6,%7},{%8,%9},{%0,%1,%2,%3};\n"
                        : "+f"(acc[mt][nt][0]), "+f"(acc[mt][nt][1]),
                          "+f"(acc[mt][nt][2]), "+f"(acc[mt][nt][3])
                        : "r"(af[mt][0]), "r"(af[mt][1]),
                          "r"(af[mt][2]), "r"(af[mt][3]),
                          "r"(b0), "r"(b1));
                }
            }
        }
        __syncthreads();
        if (t + 2 < T) { ISSUE(t + 2, buf); }
        else           { asm volatile("cp.async.commit_group;\n"); }
        asm volatile("cp.async.wait_group 1;\n");
        __syncthreads();
    }
    #undef ISSUE

    // epilogue: C layout per mma m16n8: rows r/r+8, cols 2q,2q+1
    #pragma unroll
    for (int mt = 0; mt < MT; mt++) {
        int r0 = m0 + wm + mt*16 + r;
        #pragma unroll
        for (int nt = 0; nt < NTL; nt++) {
            int cc = n0 + wn + nt*8 + c0;
            if (OUT == 2) {
                uint16_t* C8 = (uint16_t*)Cv;  // e4m3-packed, N/2 u16 per row
                if (r0 < M)
                    C8[(size_t)r0 * (N/2) + cc/2] =
                        f2_to_fp8x2(acc[mt][nt][0], acc[mt][nt][1]);
                if (r0 + 8 < M)
                    C8[(size_t)(r0 + 8) * (N/2) + cc/2] =
                        f2_to_fp8x2(acc[mt][nt][2], acc[mt][nt][3]);
            } else {
                uint32_t* Cb = (uint32_t*)Cv;  // bf16x2-packed, N/2 u32 per row
                if (r0 < M)
                    Cb[(size_t)r0 * (N/2) + cc/2] =
                        f2_to_bf2x(acc[mt][nt][0], acc[mt][nt][1]);
                if (r0 + 8 < M)
                    Cb[(size_t)(r0 + 8) * (N/2) + cc/2] =
                        f2_to_bf2x(acc[mt][nt][2], acc[mt][nt][3]);
            }
        }
    }
}

// ---------------------------------------------------------------------------
// SpMM F=256 over fp8 support: 2 rows per 128-block, 64 threads/row,
// each thread covers 4 features (one u32 gather / edge).
// out = bf16( relu( sum val*sup[col] + bias ) )  (fp32 accumulate)
// ---------------------------------------------------------------------------
__global__ __launch_bounds__(128) void k_spmm256_f8(
    const uint32_t* __restrict__ sup8, const float* __restrict__ bias,
    uint32_t* __restrict__ out)
{
    int t64 = threadIdx.x & 63;
    int row = blockIdx.x * 2 + (threadIdx.x >> 6);
    int s = g_rowptr[row], e = g_rowptr[row + 1];

    float a0 = 0.f, a1 = 0.f, a2 = 0.f, a3 = 0.f;
    int i = s;
    for (; i + 4 <= e; i += 4) {
        int2 r0 = g_edge[i],     r1 = g_edge[i + 1];
        int2 r2 = g_edge[i + 2], r3 = g_edge[i + 3];
        uint32_t u0 = sup8[(size_t)r0.x * 64 + t64];
        uint32_t u1 = sup8[(size_t)r1.x * 64 + t64];
        uint32_t u2 = sup8[(size_t)r2.x * 64 + t64];
        uint32_t u3 = sup8[(size_t)r3.x * 64 + t64];
        float v0 = __int_as_float(r0.y), v1 = __int_as_float(r1.y);
        float v2 = __int_as_float(r2.y), v3 = __int_as_float(r3.y);
        {
            float2 lo = fp8x2_to_f2((uint16_t)(u0 & 0xffff));
            float2 hi = fp8x2_to_f2((uint16_t)(u0 >> 16));
            a0 = fmaf(v0, lo.x, a0); a1 = fmaf(v0, lo.y, a1);
            a2 = fmaf(v0, hi.x, a2); a3 = fmaf(v0, hi.y, a3);
        }
        {
            float2 lo = fp8x2_to_f2((uint16_t)(u1 & 0xffff));
            float2 hi = fp8x2_to_f2((uint16_t)(u1 >> 16));
            a0 = fmaf(v1, lo.x, a0); a1 = fmaf(v1, lo.y, a1);
            a2 = fmaf(v1, hi.x, a2); a3 = fmaf(v1, hi.y, a3);
        }
        {
            float2 lo = fp8x2_to_f2((uint16_t)(u2 & 0xffff));
            float2 hi = fp8x2_to_f2((uint16_t)(u2 >> 16));
            a0 = fmaf(v2, lo.x, a0); a1 = fmaf(v2, lo.y, a1);
            a2 = fmaf(v2, hi.x, a2); a3 = fmaf(v2, hi.y, a3);
        }
        {
            float2 lo = fp8x2_to_f2((uint16_t)(u3 & 0xffff));
            float2 hi = fp8x2_to_f2((uint16_t)(u3 >> 16));
            a0 = fmaf(v3, lo.x, a0); a1 = fmaf(v3, lo.y, a1);
            a2 = fmaf(v3, hi.x, a2); a3 = fmaf(v3, hi.y, a3);
        }
    }
    for (; i < e; i++) {
        int2 r = g_edge[i];
        float v = __int_as_float(r.y);
        uint32_t u = sup8[(size_t)r.x * 64 + t64];
        float2 lo = fp8x2_to_f2((uint16_t)(u & 0xffff));
        float2 hi = fp8x2_to_f2((uint16_t)(u >> 16));
        a0 = fmaf(v, lo.x, a0); a1 = fmaf(v, lo.y, a1);
        a2 = fmaf(v, hi.x, a2); a3 = fmaf(v, hi.y, a3);
    }
    float4 b = *(const float4*)&bias[4 * t64];
    uint2 o;
    o.x = f2_to_bf2x(fmaxf(a0 + b.x, 0.f), fmaxf(a1 + b.y, 0.f));
    o.y = f2_to_bf2x(fmaxf(a2 + b.z, 0.f), fmaxf(a3 + b.w, 0.f));
    *(uint2*)&out[(size_t)row * 128 + 2 * t64] = o;
}

// ---------------------------------------------------------------------------
// SpMM F=64 (bf16 support) + bias + log_softmax. Warp per row, 4 rows/block.
// ---------------------------------------------------------------------------
__global__ __launch_bounds__(128) void k_spmm64_lsm_bf(
    const uint32_t* __restrict__ supu, const float* __restrict__ b3,
    float* __restrict__ out)
{
    int lane = threadIdx.x & 31;
    int row  = blockIdx.x * 4 + (threadIdx.x >> 5);

    int s = g_rowptr[row], e = g_rowptr[row + 1];

    float ax0 = 0.f, ay0 = 0.f, ax1 = 0.f, ay1 = 0.f;
    int i = s;
    for (; i + 4 <= e; i += 4) {
        int2 r0 = g_edge[i],     r1 = g_edge[i + 1];
        int2 r2 = g_edge[i + 2], r3 = g_edge[i + 3];
        float2 f0 = bf2x_to_f2(supu[(size_t)r0.x * 32 + lane]);
        float2 f1 = bf2x_to_f2(supu[(size_t)r1.x * 32 + lane]);
        float2 f2 = bf2x_to_f2(supu[(size_t)r2.x * 32 + lane]);
        float2 f3 = bf2x_to_f2(supu[(size_t)r3.x * 32 + lane]);
        float v0 = __int_as_float(r0.y), v1 = __int_as_float(r1.y);
        float v2 = __int_as_float(r2.y), v3 = __int_as_float(r3.y);
        ax0 = fmaf(v0, f0.x, ax0); ay0 = fmaf(v0, f0.y, ay0);
        ax1 = fmaf(v1, f1.x, ax1); ay1 = fmaf(v1, f1.y, ay1);
        ax0 = fmaf(v2, f2.x, ax0); ay0 = fmaf(v2, f2.y, ay0);
        ax1 = fmaf(v3, f3.x, ax1); ay1 = fmaf(v3, f3.y, ay1);
    }
    for (; i < e; i++) {
        int2 r = g_edge[i];
        float v = __int_as_float(r.y);
        float2 f = bf2x_to_f2(supu[(size_t)r.x * 32 + lane]);
        ax0 = fmaf(v, f.x, ax0); ay0 = fmaf(v, f.y, ay0);
    }
    float2 b = *(const float2*)&b3[2 * lane];
    float rx = ax0 + ax1 + b.x;
    float ry = ay0 + ay1 + b.y;

    // warp log-softmax over 64 values (2 per lane)
    float m = fmaxf(rx, ry);
    #pragma unroll
    for (int o = 16; o > 0; o >>= 1)
        m = fmaxf(m, __shfl_xor_sync(0xFFFFFFFFu, m, o));
    float sum = expf(rx - m) + expf(ry - m);
    #pragma unroll
    for (int o = 16; o > 0; o >>= 1)
        sum += __shfl_xor_sync(0xFFFFFFFFu, sum, o);
    float ls = m + logf(sum);

    float2 o2 = make_float2(rx - ls, ry - ls);
    *(float2*)&out[(size_t)row * 64 + 2 * lane] = o2;
}

// ---------------------------------------------------------------------------
// Launch — forked graph: CSR build runs concurrently with cvt+GEMM1.
// ---------------------------------------------------------------------------
extern "C" void kernel_launch(void* const* d_in, const int* in_sizes, int n_in,
                              void* d_out, int out_size)
{
    const float* x    = (const float*)d_in[0];
    const int*   erow = (const int*)  d_in[1];
    const int*   ecol = (const int*)  d_in[2];
    const float* eval = (const float*)d_in[3];
    const float* W1   = (const float*)d_in[4];
    const float* b1   = (const float*)d_in[5];
    const float* W2   = (const float*)d_in[6];
    const float* b2   = (const float*)d_in[7];
    const float* W3   = (const float*)d_in[8];
    const float* b3   = (const float*)d_in[9];
    float* out = (float*)d_out;

    uint16_t *dXbf, *dW1t, *dW2t, *dW3t;
    uint32_t *dS8, *dHbf, *dCbf;
    int *dCur;
    cudaGetSymbolAddress((void**)&dXbf, g_Xbf);
    cudaGetSymbolAddress((void**)&dS8,  g_S8);
    cudaGetSymbolAddress((void**)&dHbf, g_Hbf);
    cudaGetSymbolAddress((void**)&dCbf, g_Cbf);
    cudaGetSymbolAddress((void**)&dW1t, g_W1t);
    cudaGetSymbolAddress((void**)&dW2t, g_W2t);
    cudaGetSymbolAddress((void**)&dW3t, g_W3t);
    cudaGetSymbolAddress((void**)&dCur, g_cursor);

    // one-time host resources (created on the uncaptured correctness call,
    // reused under capture; launched work is identical every call)
    static cudaStream_t s_side = nullptr;
    static cudaEvent_t  evFork = nullptr, evJoin = nullptr;
    if (!s_side) {
        cudaStreamCreateWithFlags(&s_side, cudaStreamNonBlocking);
        cudaEventCreateWithFlags(&evFork, cudaEventDisableTiming);
        cudaEventCreateWithFlags(&evJoin, cudaEventDisableTiming);
    }

    const int NB_SCAN = (NN + 1 + 1023) / 1024;
    const int EB = (EE + 255) / 256;
    const int MB = (NN + 127) / 128;

    // ---- fork: side stream takes CSR build + W2/W3 conversions ----
    cudaEventRecord(evFork, 0);
    cudaStreamWaitEvent(s_side, evFork, 0);

    // side stream: CSR chain (independent of x / GEMM1)
    k_zero_int<<<(NN + 255) / 256, 256, 0, s_side>>>(dCur, NN);
    k_hist<<<EB, 256, 0, s_side>>>(erow);
    k_scan_block<<<NB_SCAN, 1024, 0, s_side>>>(NN + 1);
    k_scan_spine<<<1, 128, 0, s_side>>>(NB_SCAN);
    k_scan_add<<<NB_SCAN, 1024, 0, s_side>>>(NN + 1);   // also seeds cursor
    k_scatter<<<EB, 256, 0, s_side>>>(erow, ecol, eval);
    k_cvt_wt<<<(F1*F2 + 255) / 256, 256, 0, s_side>>>(W2, dW2t, F1, F2);
    k_cvt_wt<<<(F2*F3 + 255) / 256, 256, 0, s_side>>>(W3, dW3t, F2, F3);
    cudaEventRecord(evJoin, s_side);

    // main stream: x -> bf16, W1, GEMM1 (concurrent with CSR build)
    {
        int n8 = NN * F0 / 8;
        k_cvt_x_bf<<<(n8 + 255) / 256, 256>>>(x, dXbf, n8);
        k_cvt_wt<<<(F0*F1 + 255) / 256, 256>>>(W1, dW1t, F0, F1);
    }
    k_gemm_bf<128,128,64,64,2><<<dim3(F1/128, MB), 128>>>(dXbf, dW1t, dS8, NN, F1, F0);

    // ---- join: spmm needs CSR; GEMM2/3 need W2t/W3t ----
    cudaStreamWaitEvent(0, evJoin, 0);

    // layer 1 aggregate
    k_spmm256_f8<<<NN/2, 128>>>(dS8, b1, dHbf);

    // layer 2
    k_gemm_bf<128,128,64,64,2><<<dim3(F2/128, MB), 128>>>((const uint16_t*)dHbf, dW2t, dS8, NN, F2, F1);
    k_spmm256_f8<<<NN/2, 128>>>(dS8, b2, dHbf);

    // layer 3 + log_softmax
    k_gemm_bf<128,64,64,32,1><<<dim3(F3/64, MB), 128>>>((const uint16_t*)dHbf, dW3t, dCbf, NN, F3, F2);
    k_spmm64_lsm_bf<<<NN/4, 128>>>(dCbf, b3, out);
}